// round 1
// baseline (speedup 1.0000x reference)
#include <cuda_runtime.h>
#include <math.h>

#define C_DIM 256
#define HW    1024
#define N_IMG 64
#define M_TOT (N_IMG * HW)   // 65536
#define EPSF  1e-5f
#define T_ITERS 10

// ---------------- scratch (device globals; no allocation allowed) ----------
__device__ float g_part[(size_t)N_IMG * 3 * 128 * 128];  // gram partials, 12.6MB
__device__ float g_gram[C_DIM * C_DIM];
__device__ float g_sigma[C_DIM * C_DIM];
__device__ float g_SN[C_DIM * C_DIM];
__device__ float g_P[C_DIM * C_DIM];
__device__ float g_T[C_DIM * C_DIM];
__device__ float g_Q[C_DIM * C_DIM];
__device__ float g_M[C_DIM * C_DIM];
__device__ float g_mean[C_DIM];
__device__ float g_bvec[C_DIM];
__device__ float g_scal[2];   // [0]=1/trace, [1]=sqrt(1/trace)

// ---------------- per-channel mean --------------------------------------
__global__ void mean_kernel(const float* __restrict__ X) {
    int c = blockIdx.x;
    int t = threadIdx.x;
    float s = 0.f;
    for (int n = 0; n < N_IMG; n++) {
        const float* p = X + ((size_t)(n * C_DIM + c)) * HW;
        for (int s0 = t; s0 < HW; s0 += 256) s += p[s0];
    }
    __shared__ float sh[256];
    sh[t] = s;
    __syncthreads();
    for (int o = 128; o > 0; o >>= 1) {
        if (t < o) sh[t] += sh[t + o];
        __syncthreads();
    }
    if (t == 0) g_mean[c] = sh[0] * (1.0f / (float)M_TOT);
}

// ---------------- Gram partials: per image n, upper-triangular 128 tiles ---
// grid (3, 64): blockIdx.x = tile pair p in {(0,0),(0,1),(1,1)}, blockIdx.y = n
__global__ void gram_kernel(const float* __restrict__ X) {
    const int p = blockIdx.x, n = blockIdx.y;
    const int bi = (p == 2) ? 1 : 0;
    const int bj = (p == 0) ? 0 : 1;

    __shared__ float As[128][17];
    __shared__ float Bs[128][17];

    const int tid = threadIdx.x;
    const int tx = tid & 15, ty = tid >> 4;

    float acc[8][8];
#pragma unroll
    for (int u = 0; u < 8; u++)
#pragma unroll
        for (int v = 0; v < 8; v++) acc[u][v] = 0.f;

    const float* Abase = X + ((size_t)n * C_DIM + bi * 128) * HW;
    const float* Bbase = X + ((size_t)n * C_DIM + bj * 128) * HW;

    for (int k0 = 0; k0 < HW; k0 += 16) {
#pragma unroll
        for (int r = 0; r < 8; r++) {
            int t2 = tid + r * 256;
            int i = t2 >> 4, k = t2 & 15;
            As[i][k] = Abase[(size_t)i * HW + k0 + k];
            Bs[i][k] = Bbase[(size_t)i * HW + k0 + k];
        }
        __syncthreads();
#pragma unroll
        for (int k = 0; k < 16; k++) {
            float a[8], b[8];
#pragma unroll
            for (int u = 0; u < 8; u++) a[u] = As[ty + 16 * u][k];
#pragma unroll
            for (int v = 0; v < 8; v++) b[v] = Bs[tx + 16 * v][k];
#pragma unroll
            for (int u = 0; u < 8; u++)
#pragma unroll
                for (int v = 0; v < 8; v++) acc[u][v] += a[u] * b[v];
        }
        __syncthreads();
    }

    float* out = g_part + ((size_t)n * 3 + p) * (128 * 128);
#pragma unroll
    for (int u = 0; u < 8; u++)
#pragma unroll
        for (int v = 0; v < 8; v++)
            out[(ty + 16 * u) * 128 + (tx + 16 * v)] = acc[u][v];
}

// reduce 64 image-partials -> full symmetric Gram (deterministic, no atomics)
// grid (3, 128), block 128
__global__ void gram_reduce_kernel() {
    const int p = blockIdx.x, i = blockIdx.y, j = threadIdx.x;
    const int bi = (p == 2) ? 1 : 0;
    const int bj = (p == 0) ? 0 : 1;
    float s = 0.f;
    for (int n = 0; n < N_IMG; n++)
        s += g_part[(((size_t)n * 3 + p) * 128 + i) * 128 + j];
    int gi = bi * 128 + i, gj = bj * 128 + j;
    g_gram[gi * C_DIM + gj] = s;
    g_gram[gj * C_DIM + gi] = s;
}

// Sigma = Gram/m - mean outer + eps I.  grid 256, block 256
__global__ void sigma_kernel() {
    int i = blockIdx.x, j = threadIdx.x;
    float v = g_gram[i * C_DIM + j] * (1.0f / (float)M_TOT) - g_mean[i] * g_mean[j];
    if (i == j) v += EPSF;
    g_sigma[i * C_DIM + j] = v;
}

// trace of Sigma -> 1/tr and sqrt(1/tr).  1 block, 256 threads
__global__ void trace_kernel() {
    int t = threadIdx.x;
    __shared__ float sh[256];
    sh[t] = g_sigma[t * (C_DIM + 1)];
    __syncthreads();
    for (int o = 128; o > 0; o >>= 1) {
        if (t < o) sh[t] += sh[t + o];
        __syncthreads();
    }
    if (t == 0) {
        float tr_rec = 1.0f / sh[0];
        g_scal[0] = tr_rec;
        g_scal[1] = sqrtf(tr_rec);
    }
}

// Sigma_N = Sigma * tr_rec ; P = I.  grid 256, block 256
__global__ void sninit_kernel() {
    int i = blockIdx.x, j = threadIdx.x;
    int idx = i * C_DIM + j;
    g_SN[idx] = g_sigma[idx] * g_scal[0];
    g_P[idx] = (i == j) ? 1.0f : 0.0f;
}

// ---------------- small 256x256x256 GEMM (32x32 tiles, 2x2/thread) -------
// mode 0: C = A@B
// mode 1: C = 1.5*C - 0.5*(A@B)   (in-place on C; each thread RMWs its own elem)
// mode 2: C = g_scal[1] * (A@B)
// blockIdx.z==1 selects the (A2,B2,C2) set (mode 0 only)
__global__ void sgemm32_kernel(const float* __restrict__ A0, const float* __restrict__ B0,
                               float* __restrict__ C0,
                               const float* __restrict__ A1, const float* __restrict__ B1,
                               float* __restrict__ C1, int mode) {
    const float* A = (blockIdx.z == 0) ? A0 : A1;
    const float* B = (blockIdx.z == 0) ? B0 : B1;
    float* C = (blockIdx.z == 0) ? C0 : C1;

    __shared__ float As[32][17];
    __shared__ float Bs[16][32];

    const int tid = threadIdx.x;
    const int tx = tid & 15, ty = tid >> 4;
    const int bi = blockIdx.x * 32, bj = blockIdx.y * 32;

    float acc00 = 0.f, acc01 = 0.f, acc10 = 0.f, acc11 = 0.f;

    for (int k0 = 0; k0 < C_DIM; k0 += 16) {
        {
            int t2 = tid;               // 512 elems of As, 2 per thread
            int i = t2 >> 4, k = t2 & 15;
            As[i][k] = A[(bi + i) * C_DIM + k0 + k];
            t2 = tid + 256;
            i = t2 >> 4; k = t2 & 15;
            As[i][k] = A[(bi + i) * C_DIM + k0 + k];
        }
        {
            int t2 = tid;               // 512 elems of Bs, 2 per thread
            int k = t2 >> 5, j = t2 & 31;
            Bs[k][j] = B[(k0 + k) * C_DIM + bj + j];
            t2 = tid + 256;
            k = t2 >> 5; j = t2 & 31;
            Bs[k][j] = B[(k0 + k) * C_DIM + bj + j];
        }
        __syncthreads();
#pragma unroll
        for (int k = 0; k < 16; k++) {
            float a0 = As[ty][k], a1 = As[ty + 16][k];
            float b0 = Bs[k][tx], b1 = Bs[k][tx + 16];
            acc00 += a0 * b0;
            acc01 += a0 * b1;
            acc10 += a1 * b0;
            acc11 += a1 * b1;
        }
        __syncthreads();
    }

    float res[2][2] = {{acc00, acc01}, {acc10, acc11}};
#pragma unroll
    for (int u = 0; u < 2; u++)
#pragma unroll
        for (int v = 0; v < 2; v++) {
            int gi = bi + ty + 16 * u, gj = bj + tx + 16 * v;
            float r = res[u][v];
            if (mode == 1) r = 1.5f * C[gi * C_DIM + gj] - 0.5f * r;
            else if (mode == 2) r = g_scal[1] * r;
            C[gi * C_DIM + gj] = r;
        }
}

// b[d] = sum_c M[d,c]*mean[c].  grid 256, block 256
__global__ void bvec_kernel() {
    int d = blockIdx.x, t = threadIdx.x;
    __shared__ float sh[256];
    sh[t] = g_M[d * C_DIM + t] * g_mean[t];
    __syncthreads();
    for (int o = 128; o > 0; o >>= 1) {
        if (t < o) sh[t] += sh[t + o];
        __syncthreads();
    }
    if (t == 0) g_bvec[d] = sh[0];
}

// ---------------- out = M @ X_n - b  (per image), 128x128 tiles ----------
// grid (2, 8, 64), block 256
__global__ void out_kernel(const float* __restrict__ X, float* __restrict__ O) {
    const int bi = blockIdx.x, bj = blockIdx.y, n = blockIdx.z;

    __shared__ float As[128][17];   // M tile  [i][k]
    __shared__ float Bs[16][128];   // X tile  [k][j]

    const int tid = threadIdx.x;
    const int tx = tid & 15, ty = tid >> 4;

    float acc[8][8];
#pragma unroll
    for (int u = 0; u < 8; u++)
#pragma unroll
        for (int v = 0; v < 8; v++) acc[u][v] = 0.f;

    for (int k0 = 0; k0 < C_DIM; k0 += 16) {
#pragma unroll
        for (int r = 0; r < 8; r++) {
            int t2 = tid + r * 256;
            int i = t2 >> 4, k = t2 & 15;
            As[i][k] = g_M[(bi * 128 + i) * C_DIM + k0 + k];
        }
#pragma unroll
        for (int r = 0; r < 8; r++) {
            int t2 = tid + r * 256;
            int k = t2 >> 7, j = t2 & 127;
            Bs[k][j] = X[((size_t)n * C_DIM + k0 + k) * HW + bj * 128 + j];
        }
        __syncthreads();
#pragma unroll
        for (int k = 0; k < 16; k++) {
            float a[8], b[8];
#pragma unroll
            for (int u = 0; u < 8; u++) a[u] = As[ty + 16 * u][k];
#pragma unroll
            for (int v = 0; v < 8; v++) b[v] = Bs[k][tx + 16 * v];
#pragma unroll
            for (int u = 0; u < 8; u++)
#pragma unroll
                for (int v = 0; v < 8; v++) acc[u][v] += a[u] * b[v];
        }
        __syncthreads();
    }

#pragma unroll
    for (int u = 0; u < 8; u++) {
        int d = bi * 128 + ty + 16 * u;
        float bb = g_bvec[d];
#pragma unroll
        for (int v = 0; v < 8; v++)
            O[((size_t)n * C_DIM + d) * HW + bj * 128 + tx + 16 * v] = acc[u][v] - bb;
    }
}

// ---------------- launcher ------------------------------------------------
extern "C" void kernel_launch(void* const* d_in, const int* in_sizes, int n_in,
                              void* d_out, int out_size) {
    (void)in_sizes; (void)n_in; (void)out_size;
    const float* X = (const float*)d_in[0];
    const float* R = (const float*)d_in[1];
    float* O = (float*)d_out;

    float *pP, *pT, *pQ, *pSN, *pM;
    cudaGetSymbolAddress((void**)&pP, g_P);
    cudaGetSymbolAddress((void**)&pT, g_T);
    cudaGetSymbolAddress((void**)&pQ, g_Q);
    cudaGetSymbolAddress((void**)&pSN, g_SN);
    cudaGetSymbolAddress((void**)&pM, g_M);

    mean_kernel<<<C_DIM, 256>>>(X);
    gram_kernel<<<dim3(3, N_IMG), 256>>>(X);
    gram_reduce_kernel<<<dim3(3, 128), 128>>>();
    sigma_kernel<<<C_DIM, 256>>>();
    trace_kernel<<<1, 256>>>();
    sninit_kernel<<<C_DIM, 256>>>();

    for (int it = 0; it < T_ITERS; it++) {
        // T = P@P  and  Q = P@SN   (independent, one launch, grid.z = 2)
        sgemm32_kernel<<<dim3(8, 8, 2), 256>>>(pP, pP, pT, pP, pSN, pQ, 0);
        // P = 1.5P - 0.5 * T@Q
        sgemm32_kernel<<<dim3(8, 8, 1), 256>>>(pT, pQ, pP, pT, pQ, pP, 1);
    }

    // M = sqrt(tr_rec) * (R @ P)
    sgemm32_kernel<<<dim3(8, 8, 1), 256>>>(R, pP, pM, R, pP, pM, 2);
    bvec_kernel<<<C_DIM, 256>>>();
    out_kernel<<<dim3(2, 8, N_IMG), 256>>>(X, O);
}

// round 4
// speedup vs baseline: 1.5266x; 1.5266x over previous
#include <cuda_runtime.h>
#include <cuda_bf16.h>
#include <stdint.h>
#include <math.h>

#define C_DIM 256
#define HW    1024
#define N_IMG 64
#define M_TOT (N_IMG * HW)   // 65536
#define EPSF  1e-5f
#define T_ITERS 10

// pad bf16 tile rows to 72 elems (144B = 36 banks) -> conflict-free frag loads
#define PADK 72

// ---------------- scratch (device globals; no allocation allowed) ----------
__device__ float g_part[(size_t)3 * N_IMG * 128 * 128];  // gram partials 12.6MB
__device__ float g_gram[C_DIM * C_DIM];
__device__ float g_sigma[C_DIM * C_DIM];
__device__ float g_SN[C_DIM * C_DIM];
__device__ float g_P[C_DIM * C_DIM];
__device__ float g_T[C_DIM * C_DIM];
__device__ float g_Q[C_DIM * C_DIM];
__device__ float g_M[C_DIM * C_DIM];
__device__ __nv_bfloat16 g_Mhi[C_DIM * C_DIM];
__device__ __nv_bfloat16 g_Mlo[C_DIM * C_DIM];
__device__ float g_mean[C_DIM];
__device__ float g_bvec[C_DIM];
__device__ float g_scal[2];   // [0]=1/trace, [1]=sqrt(1/trace)

// ======================= mma.sync helpers =================================
__device__ __forceinline__ void mma_bf16(float* c, const uint32_t* a, const uint32_t* b) {
    asm volatile(
        "mma.sync.aligned.m16n8k16.row.col.f32.bf16.bf16.f32 "
        "{%0,%1,%2,%3}, {%4,%5,%6,%7}, {%8,%9}, {%0,%1,%2,%3};"
        : "+f"(c[0]), "+f"(c[1]), "+f"(c[2]), "+f"(c[3])
        : "r"(a[0]), "r"(a[1]), "r"(a[2]), "r"(a[3]), "r"(b[0]), "r"(b[1]));
}
__device__ __forceinline__ uint32_t packbf2(__nv_bfloat16 a, __nv_bfloat16 b) {
    return (uint32_t)__bfloat16_as_ushort(a) | ((uint32_t)__bfloat16_as_ushort(b) << 16);
}
__device__ __forceinline__ void split1(float x, __nv_bfloat16& h, __nv_bfloat16& l) {
    h = __float2bfloat16(x);
    l = __float2bfloat16(x - __bfloat162float(h));
}
// load A fragment (m16 x k16) from padded bf16 smem tile, row-major K-contig
__device__ __forceinline__ void lda(uint32_t* a, const __nv_bfloat16* t,
                                    int row, int k, int l4, int q2) {
    const __nv_bfloat16* p = t + (row + l4) * PADK + k + q2;
    a[0] = *(const uint32_t*)p;
    a[1] = *(const uint32_t*)(p + 8 * PADK);
    a[2] = *(const uint32_t*)(p + 8);
    a[3] = *(const uint32_t*)(p + 8 * PADK + 8);
}
// load B fragment (n8 x k16)
__device__ __forceinline__ void ldb(uint32_t* b, const __nv_bfloat16* t,
                                    int n, int k, int l4, int q2) {
    const __nv_bfloat16* p = t + (n + l4) * PADK + k + q2;
    b[0] = *(const uint32_t*)p;
    b[1] = *(const uint32_t*)(p + 8);
}

// ---------------- per-channel mean --------------------------------------
__global__ void mean_kernel(const float* __restrict__ X) {
    int c = blockIdx.x;
    int t = threadIdx.x;
    float s = 0.f;
    for (int n = 0; n < N_IMG; n++) {
        const float* p = X + ((size_t)(n * C_DIM + c)) * HW;
        for (int s0 = t; s0 < HW; s0 += 256) s += p[s0];
    }
    __shared__ float sh[256];
    sh[t] = s;
    __syncthreads();
    for (int o = 128; o > 0; o >>= 1) {
        if (t < o) sh[t] += sh[t + o];
        __syncthreads();
    }
    if (t == 0) g_mean[c] = sh[0] * (1.0f / (float)M_TOT);
}

// ================= Gram via mma.sync, bf16 hi/lo split ====================
// grid (3 pairs, 64 images), 256 threads. Each CTA: 128x128 tile, K=1024.
// pairs: 0=(0,0) 1=(0,1) 2=(1,1); diag pairs reuse A tiles as B.
__global__ __launch_bounds__(256, 1)
void gram_mma(const float* __restrict__ X) {
    extern __shared__ char sm[];
    const int p = blockIdx.x, n = blockIdx.y;
    const int bi = (p == 2) ? 1 : 0;
    const int bj = (p == 0) ? 0 : 1;
    const bool diag = (bi == bj);

    __nv_bfloat16* AHI = (__nv_bfloat16*)sm;                 // 128*72
    __nv_bfloat16* ALO = AHI + 128 * PADK;
    __nv_bfloat16* BHI = ALO + 128 * PADK;
    __nv_bfloat16* BLO = BHI + 128 * PADK;

    const int tid = threadIdx.x, w = tid >> 5, lane = tid & 31;
    const int wm = w >> 2, wn = w & 3;           // warp tile: 64m x 32n
    const int l4 = lane >> 2, q2 = (lane & 3) * 2;

    float acc[4][4][4];
#pragma unroll
    for (int i = 0; i < 4; i++)
#pragma unroll
        for (int j = 0; j < 4; j++)
#pragma unroll
            for (int r = 0; r < 4; r++) acc[i][j][r] = 0.f;

    const __nv_bfloat16* Bh = diag ? AHI : BHI;
    const __nv_bfloat16* Bl = diag ? ALO : BLO;

    for (int kc = 0; kc < 16; kc++) {            // 16 chunks of 64
        const int k0g = kc * 64;
        // stage operand(s): 128 rows x 64 k, fp32 -> bf16 hi/lo
#pragma unroll
        for (int it = 0; it < 8; it++) {
            int e = it * 256 + tid;              // 2048 float4
            int row = e >> 4, f4 = e & 15;
            float4 v = *(const float4*)(X + ((size_t)(n * C_DIM + bi * 128 + row)) * HW + k0g + f4 * 4);
            __nv_bfloat16 h0, h1, h2, h3, l0, l1, l2, l3;
            split1(v.x, h0, l0); split1(v.y, h1, l1);
            split1(v.z, h2, l2); split1(v.w, h3, l3);
            *(uint2*)(AHI + row * PADK + f4 * 4) = make_uint2(packbf2(h0, h1), packbf2(h2, h3));
            *(uint2*)(ALO + row * PADK + f4 * 4) = make_uint2(packbf2(l0, l1), packbf2(l2, l3));
        }
        if (!diag) {
#pragma unroll
            for (int it = 0; it < 8; it++) {
                int e = it * 256 + tid;
                int row = e >> 4, f4 = e & 15;
                float4 v = *(const float4*)(X + ((size_t)(n * C_DIM + bj * 128 + row)) * HW + k0g + f4 * 4);
                __nv_bfloat16 h0, h1, h2, h3, l0, l1, l2, l3;
                split1(v.x, h0, l0); split1(v.y, h1, l1);
                split1(v.z, h2, l2); split1(v.w, h3, l3);
                *(uint2*)(BHI + row * PADK + f4 * 4) = make_uint2(packbf2(h0, h1), packbf2(h2, h3));
                *(uint2*)(BLO + row * PADK + f4 * 4) = make_uint2(packbf2(l0, l1), packbf2(l2, l3));
            }
        }
        __syncthreads();
#pragma unroll
        for (int ks = 0; ks < 4; ks++) {
            const int k0 = ks * 16;
            uint32_t bh[4][2], bl[4][2];
#pragma unroll
            for (int nt = 0; nt < 4; nt++) {
                ldb(bh[nt], Bh, wn * 32 + nt * 8, k0, l4, q2);
                ldb(bl[nt], Bl, wn * 32 + nt * 8, k0, l4, q2);
            }
#pragma unroll
            for (int mt = 0; mt < 4; mt++) {
                uint32_t ah[4], al[4];
                lda(ah, AHI, wm * 64 + mt * 16, k0, l4, q2);
                lda(al, ALO, wm * 64 + mt * 16, k0, l4, q2);
#pragma unroll
                for (int nt = 0; nt < 4; nt++) {
                    mma_bf16(acc[mt][nt], ah, bh[nt]);
                    mma_bf16(acc[mt][nt], ah, bl[nt]);
                    mma_bf16(acc[mt][nt], al, bh[nt]);
                }
            }
        }
        __syncthreads();
    }

    float* outp = g_part + ((size_t)p * N_IMG + n) * 16384;
#pragma unroll
    for (int mt = 0; mt < 4; mt++)
#pragma unroll
        for (int nt = 0; nt < 4; nt++) {
            int i0 = wm * 64 + mt * 16 + l4;
            int j0 = wn * 32 + nt * 8 + q2;
            *(float2*)(outp + i0 * 128 + j0) = make_float2(acc[mt][nt][0], acc[mt][nt][1]);
            *(float2*)(outp + (i0 + 8) * 128 + j0) = make_float2(acc[mt][nt][2], acc[mt][nt][3]);
        }
}

// reduce image-partials -> full symmetric Gram (deterministic, no atomics)
__global__ void gram_reduce_kernel() {
    const int p = blockIdx.x, i = blockIdx.y, j = threadIdx.x;
    const int bi = (p == 2) ? 1 : 0;
    const int bj = (p == 0) ? 0 : 1;
    float s = 0.f;
    for (int n = 0; n < N_IMG; n++)
        s += g_part[((size_t)p * N_IMG + n) * 16384 + i * 128 + j];
    int gi = bi * 128 + i, gj = bj * 128 + j;
    g_gram[gi * C_DIM + gj] = s;
    g_gram[gj * C_DIM + gi] = s;
}

// Sigma = Gram/m - mean outer + eps I.  grid 256, block 256
__global__ void sigma_kernel() {
    int i = blockIdx.x, j = threadIdx.x;
    float v = g_gram[i * C_DIM + j] * (1.0f / (float)M_TOT) - g_mean[i] * g_mean[j];
    if (i == j) v += EPSF;
    g_sigma[i * C_DIM + j] = v;
}

__global__ void trace_kernel() {
    int t = threadIdx.x;
    __shared__ float sh[256];
    sh[t] = g_sigma[t * (C_DIM + 1)];
    __syncthreads();
    for (int o = 128; o > 0; o >>= 1) {
        if (t < o) sh[t] += sh[t + o];
        __syncthreads();
    }
    if (t == 0) {
        float tr_rec = 1.0f / sh[0];
        g_scal[0] = tr_rec;
        g_scal[1] = sqrtf(tr_rec);
    }
}

__global__ void sninit_kernel() {
    int i = blockIdx.x, j = threadIdx.x;
    int idx = i * C_DIM + j;
    g_SN[idx] = g_sigma[idx] * g_scal[0];
    g_P[idx] = (i == j) ? 1.0f : 0.0f;
}

// ---------------- small 256x256x256 fp32 GEMM (Newton loop) --------------
__global__ void sgemm32_kernel(const float* __restrict__ A0, const float* __restrict__ B0,
                               float* __restrict__ C0,
                               const float* __restrict__ A1, const float* __restrict__ B1,
                               float* __restrict__ C1, int mode) {
    const float* A = (blockIdx.z == 0) ? A0 : A1;
    const float* B = (blockIdx.z == 0) ? B0 : B1;
    float* C = (blockIdx.z == 0) ? C0 : C1;

    __shared__ float As[32][17];
    __shared__ float Bs[16][32];

    const int tid = threadIdx.x;
    const int tx = tid & 15, ty = tid >> 4;
    const int bi = blockIdx.x * 32, bj = blockIdx.y * 32;

    float acc00 = 0.f, acc01 = 0.f, acc10 = 0.f, acc11 = 0.f;

    for (int k0 = 0; k0 < C_DIM; k0 += 16) {
        {
            int i = tid >> 4, k = tid & 15;
            As[i][k] = A[(bi + i) * C_DIM + k0 + k];
            int t2 = tid + 256;
            i = t2 >> 4; k = t2 & 15;
            As[i][k] = A[(bi + i) * C_DIM + k0 + k];
        }
        {
            int k = tid >> 5, j = tid & 31;
            Bs[k][j] = B[(k0 + k) * C_DIM + bj + j];
            int t2 = tid + 256;
            k = t2 >> 5; j = t2 & 31;
            Bs[k][j] = B[(k0 + k) * C_DIM + bj + j];
        }
        __syncthreads();
#pragma unroll
        for (int k = 0; k < 16; k++) {
            float a0 = As[ty][k], a1 = As[ty + 16][k];
            float b0 = Bs[k][tx], b1 = Bs[k][tx + 16];
            acc00 += a0 * b0;
            acc01 += a0 * b1;
            acc10 += a1 * b0;
            acc11 += a1 * b1;
        }
        __syncthreads();
    }

    float res[2][2] = {{acc00, acc01}, {acc10, acc11}};
#pragma unroll
    for (int u = 0; u < 2; u++)
#pragma unroll
        for (int v = 0; v < 2; v++) {
            int gi = bi + ty + 16 * u, gj = bj + tx + 16 * v;
            float r = res[u][v];
            if (mode == 1) r = 1.5f * C[gi * C_DIM + gj] - 0.5f * r;
            else if (mode == 2) r = g_scal[1] * r;
            C[gi * C_DIM + gj] = r;
        }
}

// split M into bf16 hi/lo.  grid 256, block 256
__global__ void msplit_kernel() {
    int i = blockIdx.x, j = threadIdx.x;
    float m = g_M[i * C_DIM + j];
    __nv_bfloat16 h = __float2bfloat16(m);
    g_Mhi[i * C_DIM + j] = h;
    g_Mlo[i * C_DIM + j] = __float2bfloat16(m - __bfloat162float(h));
}

// b[d] = sum_c M[d,c]*mean[c].  grid 256, block 256
__global__ void bvec_kernel() {
    int d = blockIdx.x, t = threadIdx.x;
    __shared__ float sh[256];
    sh[t] = g_M[d * C_DIM + t] * g_mean[t];
    __syncthreads();
    for (int o = 128; o > 0; o >>= 1) {
        if (t < o) sh[t] += sh[t + o];
        __syncthreads();
    }
    if (t == 0) g_bvec[d] = sh[0];
}

// ============== Out GEMM via mma.sync: O[d,m] = M[d,:]·Xt[m,:] - b[d] =====
// grid (8 mt, 2 dh, 64 n), 256 threads. CTA output: 128d x 128m, K=256.
// A = M rows (d, c-contig, bf16 direct). B = X^T rows (m, c-contig) built by
// fp32 staging + transpose-split. D fragment: row=d, col=m -> coalesced v2 stores.
__global__ __launch_bounds__(256, 1)
void out_mma(const float* __restrict__ X, float* __restrict__ O) {
    extern __shared__ char sm[];
    const int mt = blockIdx.x, dh = blockIdx.y, n = blockIdx.z;
    const int m0g = mt * 128, d0g = dh * 128;

    float* STG = (float*)sm;                              // 64 x 132 fp32
    __nv_bfloat16* AHI = (__nv_bfloat16*)(sm + 33792);    // M hi, 128 x 72
    __nv_bfloat16* ALO = AHI + 128 * PADK;
    __nv_bfloat16* BHI = ALO + 128 * PADK;                // Xt hi, 128 x 72
    __nv_bfloat16* BLO = BHI + 128 * PADK;

    const int tid = threadIdx.x, w = tid >> 5, lane = tid & 31;
    const int wd = w >> 2, wm = w & 3;        // warp tile: 64d x 32m
    const int l4 = lane >> 2, q2 = (lane & 3) * 2;

    float acc[4][4][4];
#pragma unroll
    for (int i = 0; i < 4; i++)
#pragma unroll
        for (int j = 0; j < 4; j++)
#pragma unroll
            for (int r = 0; r < 4; r++) acc[i][j][r] = 0.f;

    for (int cc = 0; cc < 4; cc++) {          // 4 chunks of 64 channels
        const int c0 = cc * 64;
        // stage X fp32 [64c x 128m] coalesced
#pragma unroll
        for (int it = 0; it < 8; it++) {
            int e = it * 256 + tid;           // 2048 float4
            int row = e >> 5, j4 = e & 31;
            float4 v = *(const float4*)(X + ((size_t)(n * C_DIM + c0 + row)) * HW + m0g + j4 * 4);
            *(float4*)(STG + row * 132 + j4 * 4) = v;
        }
        // load M chunk bf16 -> A tiles (no transpose needed)
#pragma unroll
        for (int it = 0; it < 8; it++) {
            int e = it * 256 + tid;           // 2048 uint2 (8B = 4 bf16)
            int row = e >> 4, u = e & 15;
            *(uint2*)(AHI + row * PADK + u * 4) =
                *(const uint2*)(g_Mhi + (size_t)(d0g + row) * C_DIM + c0 + u * 4);
            *(uint2*)(ALO + row * PADK + u * 4) =
                *(const uint2*)(g_Mlo + (size_t)(d0g + row) * C_DIM + c0 + u * 4);
        }
        __syncthreads();
        // transpose-split X: B rows = m (128), cols = c (64)
        {
            int m = tid & 127, half = tid >> 7;
#pragma unroll
            for (int o = 0; o < 4; o++) {
                int ocg = half * 4 + o;
                float f[8];
#pragma unroll
                for (int kk = 0; kk < 8; kk++) f[kk] = STG[(ocg * 8 + kk) * 132 + m];
                __nv_bfloat16 h[8], l[8];
#pragma unroll
                for (int kk = 0; kk < 8; kk++) split1(f[kk], h[kk], l[kk]);
                *(uint4*)(BHI + m * PADK + ocg * 8) =
                    make_uint4(packbf2(h[0], h[1]), packbf2(h[2], h[3]),
                               packbf2(h[4], h[5]), packbf2(h[6], h[7]));
                *(uint4*)(BLO + m * PADK + ocg * 8) =
                    make_uint4(packbf2(l[0], l[1]), packbf2(l[2], l[3]),
                               packbf2(l[4], l[5]), packbf2(l[6], l[7]));
            }
        }
        __syncthreads();
#pragma unroll
        for (int ks = 0; ks < 4; ks++) {
            const int k0 = ks * 16;
            uint32_t bh[4][2], bl[4][2];
#pragma unroll
            for (int nt = 0; nt < 4; nt++) {
                ldb(bh[nt], BHI, wm * 32 + nt * 8, k0, l4, q2);
                ldb(bl[nt], BLO, wm * 32 + nt * 8, k0, l4, q2);
            }
#pragma unroll
            for (int dt = 0; dt < 4; dt++) {
                uint32_t ah[4], al[4];
                lda(ah, AHI, wd * 64 + dt * 16, k0, l4, q2);
                lda(al, ALO, wd * 64 + dt * 16, k0, l4, q2);
#pragma unroll
                for (int nt = 0; nt < 4; nt++) {
                    mma_bf16(acc[dt][nt], ah, bh[nt]);
                    mma_bf16(acc[dt][nt], ah, bl[nt]);
                    mma_bf16(acc[dt][nt], al, bh[nt]);
                }
            }
        }
        __syncthreads();
    }

    // epilogue: subtract bvec, coalesced float2 stores
    float* obase = O + (size_t)n * C_DIM * HW;
#pragma unroll
    for (int dt = 0; dt < 4; dt++) {
        int d = d0g + wd * 64 + dt * 16 + l4;
        float b0 = g_bvec[d], b8 = g_bvec[d + 8];
#pragma unroll
        for (int nt = 0; nt < 4; nt++) {
            int m = m0g + wm * 32 + nt * 8 + q2;
            *(float2*)(obase + (size_t)d * HW + m) =
                make_float2(acc[dt][nt][0] - b0, acc[dt][nt][1] - b0);
            *(float2*)(obase + (size_t)(d + 8) * HW + m) =
                make_float2(acc[dt][nt][2] - b8, acc[dt][nt][3] - b8);
        }
    }
}

// ---------------- launcher ------------------------------------------------
extern "C" void kernel_launch(void* const* d_in, const int* in_sizes, int n_in,
                              void* d_out, int out_size) {
    (void)in_sizes; (void)n_in; (void)out_size;
    const float* X = (const float*)d_in[0];
    const float* R = (const float*)d_in[1];
    float* O = (float*)d_out;

    static bool attr_done = false;
    if (!attr_done) {
        cudaFuncSetAttribute(gram_mma, cudaFuncAttributeMaxDynamicSharedMemorySize, 73728);
        cudaFuncSetAttribute(out_mma, cudaFuncAttributeMaxDynamicSharedMemorySize, 107520);
        attr_done = true;
    }

    float *pP, *pT, *pQ, *pSN, *pM;
    cudaGetSymbolAddress((void**)&pP, g_P);
    cudaGetSymbolAddress((void**)&pT, g_T);
    cudaGetSymbolAddress((void**)&pQ, g_Q);
    cudaGetSymbolAddress((void**)&pSN, g_SN);
    cudaGetSymbolAddress((void**)&pM, g_M);

    mean_kernel<<<C_DIM, 256>>>(X);
    gram_mma<<<dim3(3, N_IMG), 256, 73728>>>(X);
    gram_reduce_kernel<<<dim3(3, 128), 128>>>();
    sigma_kernel<<<C_DIM, 256>>>();
    trace_kernel<<<1, 256>>>();
    sninit_kernel<<<C_DIM, 256>>>();

    for (int it = 0; it < T_ITERS; it++) {
        sgemm32_kernel<<<dim3(8, 8, 2), 256>>>(pP, pP, pT, pP, pSN, pQ, 0);
        sgemm32_kernel<<<dim3(8, 8, 1), 256>>>(pT, pQ, pP, pT, pQ, pP, 1);
    }

    // M = sqrt(tr_rec) * (R @ P)
    sgemm32_kernel<<<dim3(8, 8, 1), 256>>>(R, pP, pM, R, pP, pM, 2);
    msplit_kernel<<<C_DIM, 256>>>();
    bvec_kernel<<<C_DIM, 256>>>();
    out_mma<<<dim3(8, 2, N_IMG), 256, 107520>>>(X, O);
}

// round 9
// speedup vs baseline: 1.5364x; 1.0064x over previous
#include <cuda_runtime.h>
#include <cuda_bf16.h>
#include <stdint.h>
#include <math.h>

#define C_DIM 256
#define HW    1024
#define N_IMG 64
#define M_TOT (N_IMG * HW)
#define EPSF  1e-5f
#define T_ITERS 10
#define PADK 72
#define NCTA 128

__device__ float g_part[(size_t)3 * N_IMG * 128 * 128];
__device__ float g_sigma[C_DIM * C_DIM];
__device__ float g_SN[C_DIM * C_DIM];
__device__ float g_P[C_DIM * C_DIM];
__device__ float g_T[C_DIM * C_DIM];
__device__ float g_Q[C_DIM * C_DIM];
__device__ float g_M[C_DIM * C_DIM];
__device__ __nv_bfloat16 g_Mhi[C_DIM * C_DIM];
__device__ __nv_bfloat16 g_Mlo[C_DIM * C_DIM];
__device__ float g_mean[C_DIM];
__device__ float g_bvec[C_DIM];
__device__ float g_scal[2];
__device__ int g_cnt;

// ======================= mma.sync helpers =================================
__device__ __forceinline__ void mma_bf16(float* c, const uint32_t* a, const uint32_t* b) {
    asm volatile(
        "mma.sync.aligned.m16n8k16.row.col.f32.bf16.bf16.f32 "
        "{%0,%1,%2,%3}, {%4,%5,%6,%7}, {%8,%9}, {%0,%1,%2,%3};"
        : "+f"(c[0]), "+f"(c[1]), "+f"(c[2]), "+f"(c[3])
        : "r"(a[0]), "r"(a[1]), "r"(a[2]), "r"(a[3]), "r"(b[0]), "r"(b[1]));
}
__device__ __forceinline__ uint32_t packbf2(__nv_bfloat16 a, __nv_bfloat16 b) {
    return (uint32_t)__bfloat16_as_ushort(a) | ((uint32_t)__bfloat16_as_ushort(b) << 16);
}
__device__ __forceinline__ void split1(float x, __nv_bfloat16& h, __nv_bfloat16& l) {
    h = __float2bfloat16(x);
    l = __float2bfloat16(x - __bfloat162float(h));
}
__device__ __forceinline__ void lda(uint32_t* a, const __nv_bfloat16* t,
                                    int row, int k, int l4, int q2) {
    const __nv_bfloat16* p = t + (row + l4) * PADK + k + q2;
    a[0] = *(const uint32_t*)p;
    a[1] = *(const uint32_t*)(p + 8 * PADK);
    a[2] = *(const uint32_t*)(p + 8);
    a[3] = *(const uint32_t*)(p + 8 * PADK + 8);
}
__device__ __forceinline__ void ldb(uint32_t* b, const __nv_bfloat16* t,
                                    int n, int k, int l4, int q2) {
    const __nv_bfloat16* p = t + (n + l4) * PADK + k + q2;
    b[0] = *(const uint32_t*)p;
    b[1] = *(const uint32_t*)(p + 8);
}

__global__ void reset_kernel() { g_cnt = 0; }
__global__ void dummy_kernel() {}

// ---------------- per-channel mean --------------------------------------
__global__ void mean_kernel(const float* __restrict__ X) {
    int c = blockIdx.x, t = threadIdx.x;
    float s = 0.f;
    for (int n = 0; n < N_IMG; n++) {
        const float* p = X + ((size_t)(n * C_DIM + c)) * HW;
        for (int s0 = t; s0 < HW; s0 += 256) s += p[s0];
    }
    __shared__ float sh[256];
    sh[t] = s;
    __syncthreads();
    for (int o = 128; o > 0; o >>= 1) {
        if (t < o) sh[t] += sh[t + o];
        __syncthreads();
    }
    if (t == 0) g_mean[c] = sh[0] * (1.0f / (float)M_TOT);
}

// ================= Gram via mma.sync (unchanged from R4) ==================
__global__ __launch_bounds__(256, 1)
void gram_mma(const float* __restrict__ X) {
    extern __shared__ char sm[];
    const int p = blockIdx.x, n = blockIdx.y;
    const int bi = (p == 2) ? 1 : 0;
    const int bj = (p == 0) ? 0 : 1;
    const bool diag = (bi == bj);

    __nv_bfloat16* AHI = (__nv_bfloat16*)sm;
    __nv_bfloat16* ALO = AHI + 128 * PADK;
    __nv_bfloat16* BHI = ALO + 128 * PADK;
    __nv_bfloat16* BLO = BHI + 128 * PADK;

    const int tid = threadIdx.x, w = tid >> 5, lane = tid & 31;
    const int wm = w >> 2, wn = w & 3;
    const int l4 = lane >> 2, q2 = (lane & 3) * 2;

    float acc[4][4][4];
#pragma unroll
    for (int i = 0; i < 4; i++)
#pragma unroll
        for (int j = 0; j < 4; j++)
#pragma unroll
            for (int r = 0; r < 4; r++) acc[i][j][r] = 0.f;

    const __nv_bfloat16* Bh = diag ? AHI : BHI;
    const __nv_bfloat16* Bl = diag ? ALO : BLO;

    for (int kc = 0; kc < 16; kc++) {
        const int k0g = kc * 64;
#pragma unroll
        for (int it = 0; it < 8; it++) {
            int e = it * 256 + tid;
            int row = e >> 4, f4 = e & 15;
            float4 v = *(const float4*)(X + ((size_t)(n * C_DIM + bi * 128 + row)) * HW + k0g + f4 * 4);
            __nv_bfloat16 h0, h1, h2, h3, l0, l1, l2, l3;
            split1(v.x, h0, l0); split1(v.y, h1, l1);
            split1(v.z, h2, l2); split1(v.w, h3, l3);
            *(uint2*)(AHI + row * PADK + f4 * 4) = make_uint2(packbf2(h0, h1), packbf2(h2, h3));
            *(uint2*)(ALO + row * PADK + f4 * 4) = make_uint2(packbf2(l0, l1), packbf2(l2, l3));
        }
        if (!diag) {
#pragma unroll
            for (int it = 0; it < 8; it++) {
                int e = it * 256 + tid;
                int row = e >> 4, f4 = e & 15;
                float4 v = *(const float4*)(X + ((size_t)(n * C_DIM + bj * 128 + row)) * HW + k0g + f4 * 4);
                __nv_bfloat16 h0, h1, h2, h3, l0, l1, l2, l3;
                split1(v.x, h0, l0); split1(v.y, h1, l1);
                split1(v.z, h2, l2); split1(v.w, h3, l3);
                *(uint2*)(BHI + row * PADK + f4 * 4) = make_uint2(packbf2(h0, h1), packbf2(h2, h3));
                *(uint2*)(BLO + row * PADK + f4 * 4) = make_uint2(packbf2(l0, l1), packbf2(l2, l3));
            }
        }
        __syncthreads();
#pragma unroll
        for (int ks = 0; ks < 4; ks++) {
            const int k0 = ks * 16;
            uint32_t bh[4][2], bl[4][2];
#pragma unroll
            for (int nt = 0; nt < 4; nt++) {
                ldb(bh[nt], Bh, wn * 32 + nt * 8, k0, l4, q2);
                ldb(bl[nt], Bl, wn * 32 + nt * 8, k0, l4, q2);
            }
#pragma unroll
            for (int mt = 0; mt < 4; mt++) {
                uint32_t ah[4], al[4];
                lda(ah, AHI, wm * 64 + mt * 16, k0, l4, q2);
                lda(al, ALO, wm * 64 + mt * 16, k0, l4, q2);
#pragma unroll
                for (int nt = 0; nt < 4; nt++) {
                    mma_bf16(acc[mt][nt], ah, bh[nt]);
                    mma_bf16(acc[mt][nt], ah, bl[nt]);
                    mma_bf16(acc[mt][nt], al, bh[nt]);
                }
            }
        }
        __syncthreads();
    }

    float* outp = g_part + ((size_t)p * N_IMG + n) * 16384;
#pragma unroll
    for (int mt = 0; mt < 4; mt++)
#pragma unroll
        for (int nt = 0; nt < 4; nt++) {
            int i0 = wm * 64 + mt * 16 + l4;
            int j0 = wn * 32 + nt * 8 + q2;
            *(float2*)(outp + i0 * 128 + j0) = make_float2(acc[mt][nt][0], acc[mt][nt][1]);
            *(float2*)(outp + (i0 + 8) * 128 + j0) = make_float2(acc[mt][nt][2], acc[mt][nt][3]);
        }
}

// =============== fused Newton cooperative kernel ==========================
__device__ __forceinline__ void gbar(int target) {
    __syncthreads();
    if (threadIdx.x == 0) {
        __threadfence();
        atomicAdd(&g_cnt, 1);
        while (*(volatile int*)&g_cnt < target) __nanosleep(32);
    }
    __syncthreads();
}

// 32x32 fp32 gemm tile; all gmem reads via __ldcg (cross-CTA within kernel)
__device__ void gtile(const float* A, const float* B, float* C,
                      int bi, int bj, int mode, float sc) {
    __shared__ float As[32][17], Bs[16][32];
    const int tid = threadIdx.x, tx = tid & 15, ty = tid >> 4;
    float a00 = 0.f, a01 = 0.f, a10 = 0.f, a11 = 0.f;
    __syncthreads();
    for (int k0 = 0; k0 < C_DIM; k0 += 16) {
        int i = tid >> 4, k = tid & 15;
        As[i][k] = __ldcg(&A[(bi + i) * C_DIM + k0 + k]);
        int t2 = tid + 256; i = t2 >> 4; k = t2 & 15;
        As[i][k] = __ldcg(&A[(bi + i) * C_DIM + k0 + k]);
        int kk = tid >> 5, j = tid & 31;
        Bs[kk][j] = __ldcg(&B[(k0 + kk) * C_DIM + bj + j]);
        t2 = tid + 256; kk = t2 >> 5; j = t2 & 31;
        Bs[kk][j] = __ldcg(&B[(k0 + kk) * C_DIM + bj + j]);
        __syncthreads();
#pragma unroll
        for (int k2 = 0; k2 < 16; k2++) {
            float x0 = As[ty][k2], x1 = As[ty + 16][k2];
            float y0 = Bs[k2][tx], y1 = Bs[k2][tx + 16];
            a00 += x0 * y0; a01 += x0 * y1;
            a10 += x1 * y0; a11 += x1 * y1;
        }
        __syncthreads();
    }
    float res[2][2] = {{a00, a01}, {a10, a11}};
#pragma unroll
    for (int u = 0; u < 2; u++)
#pragma unroll
        for (int v = 0; v < 2; v++) {
            int gi = bi + ty + 16 * u, gj = bj + tx + 16 * v;
            float r = res[u][v];
            if (mode == 1) r = 1.5f * __ldcg(&C[gi * C_DIM + gj]) - 0.5f * r;
            else if (mode == 2) r = sc * r;
            C[gi * C_DIM + gj] = r;
        }
}

__global__ __launch_bounds__(256, 1) void newton_fused(const float* __restrict__ R) {
    const int cta = blockIdx.x, tid = threadIdx.x;
    __shared__ float sh[256];
    int st = 0;

    // S0: gram reduce -> sigma (both symmetric halves)
    for (int e = cta * 384 + tid; e < (cta + 1) * 384; e += 256) {
        int p = e >> 14, r = e & 16383;
        int i = r >> 7, j = r & 127;
        const float* src = g_part + (size_t)p * N_IMG * 16384 + r;
        float s = 0.f;
        for (int n = 0; n < N_IMG; n++) s += src[(size_t)n * 16384];
        int bi = (p == 2) ? 1 : 0, bj = (p == 0) ? 0 : 1;
        int gi = bi * 128 + i, gj = bj * 128 + j;
        float v = s * (1.0f / (float)M_TOT) - g_mean[gi] * g_mean[gj];
        if (gi == gj) v += EPSF;
        g_sigma[gi * C_DIM + gj] = v;
        g_sigma[gj * C_DIM + gi] = v;
    }
    gbar(++st * NCTA);

    // S1: trace (CTA 0)
    if (cta == 0) {
        sh[tid] = __ldcg(&g_sigma[tid * (C_DIM + 1)]);
        __syncthreads();
        for (int o = 128; o > 0; o >>= 1) {
            if (tid < o) sh[tid] += sh[tid + o];
            __syncthreads();
        }
        if (tid == 0) {
            float tr = 1.0f / sh[0];
            g_scal[0] = tr;
            g_scal[1] = sqrtf(tr);
        }
    }
    gbar(++st * NCTA);

    // S2: SN = sigma * tr_rec, P = I
    {
        float s0 = __ldcg(&g_scal[0]);
        for (int e = cta * 512 + tid; e < (cta + 1) * 512; e += 256) {
            int i = e >> 8, j = e & 255;
            g_SN[e] = __ldcg(&g_sigma[e]) * s0;
            g_P[e] = (i == j) ? 1.0f : 0.0f;
        }
    }
    gbar(++st * NCTA);

    const int t64 = cta & 63;
    const int bi = (t64 >> 3) * 32, bj = (t64 & 7) * 32;
    for (int it = 0; it < T_ITERS; it++) {
        // stage A: 128 tasks: T = P@P (cta<64), Q = P@SN (cta>=64)
        {
            const float* B = (cta < 64) ? g_P : g_SN;
            float* C = (cta < 64) ? g_T : g_Q;
            gtile(g_P, B, C, bi, bj, 0, 0.f);
        }
        gbar(++st * NCTA);
        // stage B: P = 1.5P - 0.5 T@Q (64 tasks)
        if (cta < 64) gtile(g_T, g_Q, g_P, bi, bj, 1, 0.f);
        gbar(++st * NCTA);
    }

    // M = sqrt(tr_rec) * R @ P
    if (cta < 64) gtile(R, g_P, g_M, bi, bj, 2, __ldcg(&g_scal[1]));
    gbar(++st * NCTA);

    // msplit
    for (int e = cta * 512 + tid; e < (cta + 1) * 512; e += 256) {
        float m = __ldcg(&g_M[e]);
        __nv_bfloat16 h = __float2bfloat16(m);
        g_Mhi[e] = h;
        g_Mlo[e] = __float2bfloat16(m - __bfloat162float(h));
    }
    // bvec: 2 rows per CTA
    for (int rr = 0; rr < 2; rr++) {
        int d = cta * 2 + rr;
        __syncthreads();
        sh[tid] = __ldcg(&g_M[d * C_DIM + tid]) * g_mean[tid];
        __syncthreads();
        for (int o = 128; o > 0; o >>= 1) {
            if (tid < o) sh[tid] += sh[tid + o];
            __syncthreads();
        }
        if (tid == 0) g_bvec[d] = sh[0];
    }
}

// ============== Out GEMM: both d-halves per CTA, X read once ==============
// grid (8 mt, 64 n), 256 threads. CTA output: 256d x 128m, K=256.
__global__ __launch_bounds__(256, 1)
void out_mma(const float* __restrict__ X, float* __restrict__ O) {
    extern __shared__ char sm[];
    const int mt = blockIdx.x, n = blockIdx.y;
    const int m0g = mt * 128;

    float* STG = (float*)sm;                               // 64 x 132 fp32
    __nv_bfloat16* A0HI = (__nv_bfloat16*)(sm + 33792);
    __nv_bfloat16* A0LO = A0HI + 128 * PADK;
    __nv_bfloat16* A1HI = A0LO + 128 * PADK;
    __nv_bfloat16* A1LO = A1HI + 128 * PADK;
    __nv_bfloat16* BHI  = A1LO + 128 * PADK;
    __nv_bfloat16* BLO  = BHI + 128 * PADK;

    const int tid = threadIdx.x, w = tid >> 5, lane = tid & 31;
    const int wd = w >> 2, wm = w & 3;
    const int l4 = lane >> 2, q2 = (lane & 3) * 2;

    float acc[2][4][4][4];
#pragma unroll
    for (int h = 0; h < 2; h++)
#pragma unroll
        for (int i = 0; i < 4; i++)
#pragma unroll
            for (int j = 0; j < 4; j++)
#pragma unroll
                for (int r = 0; r < 4; r++) acc[h][i][j][r] = 0.f;

    for (int cc = 0; cc < 4; cc++) {
        const int c0 = cc * 64;
#pragma unroll
        for (int it = 0; it < 8; it++) {
            int e = it * 256 + tid;
            int row = e >> 5, j4 = e & 31;
            float4 v = *(const float4*)(X + ((size_t)(n * C_DIM + c0 + row)) * HW + m0g + j4 * 4);
            *(float4*)(STG + row * 132 + j4 * 4) = v;
        }
#pragma unroll
        for (int dh = 0; dh < 2; dh++) {
            __nv_bfloat16* AH = dh ? A1HI : A0HI;
            __nv_bfloat16* AL = dh ? A1LO : A0LO;
#pragma unroll
            for (int it = 0; it < 8; it++) {
                int e = it * 256 + tid;
                int row = e >> 4, u = e & 15;
                *(uint2*)(AH + row * PADK + u * 4) =
                    *(const uint2*)(g_Mhi + (size_t)(dh * 128 + row) * C_DIM + c0 + u * 4);
                *(uint2*)(AL + row * PADK + u * 4) =
                    *(const uint2*)(g_Mlo + (size_t)(dh * 128 + row) * C_DIM + c0 + u * 4);
            }
        }
        __syncthreads();
        {
            int m = tid & 127, half = tid >> 7;
#pragma unroll
            for (int o = 0; o < 4; o++) {
                int ocg = half * 4 + o;
                float f[8];
#pragma unroll
                for (int kk = 0; kk < 8; kk++) f[kk] = STG[(ocg * 8 + kk) * 132 + m];
                __nv_bfloat16 h[8], l[8];
#pragma unroll
                for (int kk = 0; kk < 8; kk++) split1(f[kk], h[kk], l[kk]);
                *(uint4*)(BHI + m * PADK + ocg * 8) =
                    make_uint4(packbf2(h[0], h[1]), packbf2(h[2], h[3]),
                               packbf2(h[4], h[5]), packbf2(h[6], h[7]));
                *(uint4*)(BLO + m * PADK + ocg * 8) =
                    make_uint4(packbf2(l[0], l[1]), packbf2(l[2], l[3]),
                               packbf2(l[4], l[5]), packbf2(l[6], l[7]));
            }
        }
        __syncthreads();
#pragma unroll
        for (int ks = 0; ks < 4; ks++) {
            const int k0 = ks * 16;
            uint32_t bh[4][2], bl[4][2];
#pragma unroll
            for (int nt = 0; nt < 4; nt++) {
                ldb(bh[nt], BHI, wm * 32 + nt * 8, k0, l4, q2);
                ldb(bl[nt], BLO, wm * 32 + nt * 8, k0, l4, q2);
            }
#pragma unroll
            for (int dh = 0; dh < 2; dh++) {
                const __nv_bfloat16* AH = dh ? A1HI : A0HI;
                const __nv_bfloat16* AL = dh ? A1LO : A0LO;
#pragma unroll
                for (int dt = 0; dt < 4; dt++) {
                    uint32_t ah[4], al[4];
                    lda(ah, AH, wd * 64 + dt * 16, k0, l4, q2);
                    lda(al, AL, wd * 64 + dt * 16, k0, l4, q2);
#pragma unroll
                    for (int nt = 0; nt < 4; nt++) {
                        mma_bf16(acc[dh][dt][nt], ah, bh[nt]);
                        mma_bf16(acc[dh][dt][nt], ah, bl[nt]);
                        mma_bf16(acc[dh][dt][nt], al, bh[nt]);
                    }
                }
            }
        }
        __syncthreads();
    }

    float* obase = O + (size_t)n * C_DIM * HW;
#pragma unroll
    for (int dh = 0; dh < 2; dh++)
#pragma unroll
        for (int dt = 0; dt < 4; dt++) {
            int d = dh * 128 + wd * 64 + dt * 16 + l4;
            float b0 = g_bvec[d], b8 = g_bvec[d + 8];
#pragma unroll
            for (int nt = 0; nt < 4; nt++) {
                int m = m0g + wm * 32 + nt * 8 + q2;
                *(float2*)(obase + (size_t)d * HW + m) =
                    make_float2(acc[dh][dt][nt][0] - b0, acc[dh][dt][nt][1] - b0);
                *(float2*)(obase + (size_t)(d + 8) * HW + m) =
                    make_float2(acc[dh][dt][nt][2] - b8, acc[dh][dt][nt][3] - b8);
            }
        }
}

// ---------------- launcher ------------------------------------------------
extern "C" void kernel_launch(void* const* d_in, const int* in_sizes, int n_in,
                              void* d_out, int out_size) {
    (void)in_sizes; (void)n_in; (void)out_size;
    const float* X = (const float*)d_in[0];
    const float* R = (const float*)d_in[1];
    float* O = (float*)d_out;

    cudaFuncSetAttribute(gram_mma, cudaFuncAttributeMaxDynamicSharedMemorySize, 73728);
    cudaFuncSetAttribute(out_mma, cudaFuncAttributeMaxDynamicSharedMemorySize, 144384);

    reset_kernel<<<1, 1>>>();
    mean_kernel<<<C_DIM, 256>>>(X);
    gram_mma<<<dim3(3, N_IMG), 256, 73728>>>(X);
    newton_fused<<<NCTA, 256>>>(R);
    dummy_kernel<<<1, 1>>>();
    out_mma<<<dim3(8, N_IMG), 256, 144384>>>(X, O);
}

// round 14
// speedup vs baseline: 1.7654x; 1.1490x over previous
#include <cuda_runtime.h>
#include <cuda_bf16.h>
#include <stdint.h>
#include <math.h>

#define C_DIM 256
#define HW    1024
#define N_IMG 64
#define M_TOT (N_IMG * HW)
#define EPSF  1e-5f
#define T_ITERS 10
#define PADK 72
#define NCTA 32

__device__ float g_part[(size_t)3 * N_IMG * 128 * 128];
__device__ float g_sigma[C_DIM * C_DIM];
__device__ float g_SN[C_DIM * C_DIM];
__device__ float g_P[C_DIM * C_DIM];
__device__ float g_T[C_DIM * C_DIM];
__device__ float g_QT[C_DIM * C_DIM];
__device__ float g_M[C_DIM * C_DIM];
__device__ __nv_bfloat16 g_Mhi[C_DIM * C_DIM];
__device__ __nv_bfloat16 g_Mlo[C_DIM * C_DIM];
__device__ float g_mean[C_DIM];
__device__ float g_bvec[C_DIM];
__device__ float g_scal[2];
__device__ int g_cnt;

// ======================= mma.sync helpers =================================
__device__ __forceinline__ void mma_bf16(float* c, const uint32_t* a, const uint32_t* b) {
    asm volatile(
        "mma.sync.aligned.m16n8k16.row.col.f32.bf16.bf16.f32 "
        "{%0,%1,%2,%3}, {%4,%5,%6,%7}, {%8,%9}, {%0,%1,%2,%3};"
        : "+f"(c[0]), "+f"(c[1]), "+f"(c[2]), "+f"(c[3])
        : "r"(a[0]), "r"(a[1]), "r"(a[2]), "r"(a[3]), "r"(b[0]), "r"(b[1]));
}
__device__ __forceinline__ uint32_t packbf2(__nv_bfloat16 a, __nv_bfloat16 b) {
    return (uint32_t)__bfloat16_as_ushort(a) | ((uint32_t)__bfloat16_as_ushort(b) << 16);
}
__device__ __forceinline__ void split1(float x, __nv_bfloat16& h, __nv_bfloat16& l) {
    h = __float2bfloat16(x);
    l = __float2bfloat16(x - __bfloat162float(h));
}
__device__ __forceinline__ void lda(uint32_t* a, const __nv_bfloat16* t,
                                    int row, int k, int l4, int q2) {
    const __nv_bfloat16* p = t + (row + l4) * PADK + k + q2;
    a[0] = *(const uint32_t*)p;
    a[1] = *(const uint32_t*)(p + 8 * PADK);
    a[2] = *(const uint32_t*)(p + 8);
    a[3] = *(const uint32_t*)(p + 8 * PADK + 8);
}
__device__ __forceinline__ void ldb(uint32_t* b, const __nv_bfloat16* t,
                                    int n, int k, int l4, int q2) {
    const __nv_bfloat16* p = t + (n + l4) * PADK + k + q2;
    b[0] = *(const uint32_t*)p;
    b[1] = *(const uint32_t*)(p + 8);
}

__global__ void reset_kernel() { g_cnt = 0; }
__global__ void dummy_kernel() {}

// ---------------- per-channel mean --------------------------------------
__global__ void mean_kernel(const float* __restrict__ X) {
    int c = blockIdx.x, t = threadIdx.x;
    float s = 0.f;
    for (int n = 0; n < N_IMG; n++) {
        const float* p = X + ((size_t)(n * C_DIM + c)) * HW;
        for (int s0 = t; s0 < HW; s0 += 256) s += p[s0];
    }
    __shared__ float sh[256];
    sh[t] = s;
    __syncthreads();
    for (int o = 128; o > 0; o >>= 1) {
        if (t < o) sh[t] += sh[t + o];
        __syncthreads();
    }
    if (t == 0) g_mean[c] = sh[0] * (1.0f / (float)M_TOT);
}

// ================= Gram via mma.sync (proven R4 path) =====================
__global__ __launch_bounds__(256, 1)
void gram_mma(const float* __restrict__ X) {
    extern __shared__ char sm[];
    const int p = blockIdx.x, n = blockIdx.y;
    const int bi = (p == 2) ? 1 : 0;
    const int bj = (p == 0) ? 0 : 1;
    const bool diag = (bi == bj);

    __nv_bfloat16* AHI = (__nv_bfloat16*)sm;
    __nv_bfloat16* ALO = AHI + 128 * PADK;
    __nv_bfloat16* BHI = ALO + 128 * PADK;
    __nv_bfloat16* BLO = BHI + 128 * PADK;

    const int tid = threadIdx.x, w = tid >> 5, lane = tid & 31;
    const int wm = w >> 2, wn = w & 3;
    const int l4 = lane >> 2, q2 = (lane & 3) * 2;

    float acc[4][4][4];
#pragma unroll
    for (int i = 0; i < 4; i++)
#pragma unroll
        for (int j = 0; j < 4; j++)
#pragma unroll
            for (int r = 0; r < 4; r++) acc[i][j][r] = 0.f;

    const __nv_bfloat16* Bh = diag ? AHI : BHI;
    const __nv_bfloat16* Bl = diag ? ALO : BLO;

    for (int kc = 0; kc < 16; kc++) {
        const int k0g = kc * 64;
#pragma unroll
        for (int it = 0; it < 8; it++) {
            int e = it * 256 + tid;
            int row = e >> 4, f4 = e & 15;
            float4 v = *(const float4*)(X + ((size_t)(n * C_DIM + bi * 128 + row)) * HW + k0g + f4 * 4);
            __nv_bfloat16 h0, h1, h2, h3, l0, l1, l2, l3;
            split1(v.x, h0, l0); split1(v.y, h1, l1);
            split1(v.z, h2, l2); split1(v.w, h3, l3);
            *(uint2*)(AHI + row * PADK + f4 * 4) = make_uint2(packbf2(h0, h1), packbf2(h2, h3));
            *(uint2*)(ALO + row * PADK + f4 * 4) = make_uint2(packbf2(l0, l1), packbf2(l2, l3));
        }
        if (!diag) {
#pragma unroll
            for (int it = 0; it < 8; it++) {
                int e = it * 256 + tid;
                int row = e >> 4, f4 = e & 15;
                float4 v = *(const float4*)(X + ((size_t)(n * C_DIM + bj * 128 + row)) * HW + k0g + f4 * 4);
                __nv_bfloat16 h0, h1, h2, h3, l0, l1, l2, l3;
                split1(v.x, h0, l0); split1(v.y, h1, l1);
                split1(v.z, h2, l2); split1(v.w, h3, l3);
                *(uint2*)(BHI + row * PADK + f4 * 4) = make_uint2(packbf2(h0, h1), packbf2(h2, h3));
                *(uint2*)(BLO + row * PADK + f4 * 4) = make_uint2(packbf2(l0, l1), packbf2(l2, l3));
            }
        }
        __syncthreads();
#pragma unroll
        for (int ks = 0; ks < 4; ks++) {
            const int k0 = ks * 16;
            uint32_t bh[4][2], bl[4][2];
#pragma unroll
            for (int nt = 0; nt < 4; nt++) {
                ldb(bh[nt], Bh, wn * 32 + nt * 8, k0, l4, q2);
                ldb(bl[nt], Bl, wn * 32 + nt * 8, k0, l4, q2);
            }
#pragma unroll
            for (int mt = 0; mt < 4; mt++) {
                uint32_t ah[4], al[4];
                lda(ah, AHI, wm * 64 + mt * 16, k0, l4, q2);
                lda(al, ALO, wm * 64 + mt * 16, k0, l4, q2);
#pragma unroll
                for (int nt = 0; nt < 4; nt++) {
                    mma_bf16(acc[mt][nt], ah, bh[nt]);
                    mma_bf16(acc[mt][nt], ah, bl[nt]);
                    mma_bf16(acc[mt][nt], al, bh[nt]);
                }
            }
        }
        __syncthreads();
    }

    float* outp = g_part + ((size_t)p * N_IMG + n) * 16384;
#pragma unroll
    for (int mt = 0; mt < 4; mt++)
#pragma unroll
        for (int nt = 0; nt < 4; nt++) {
            int i0 = wm * 64 + mt * 16 + l4;
            int j0 = wn * 32 + nt * 8 + q2;
            *(float2*)(outp + i0 * 128 + j0) = make_float2(acc[mt][nt][0], acc[mt][nt][1]);
            *(float2*)(outp + (i0 + 8) * 128 + j0) = make_float2(acc[mt][nt][2], acc[mt][nt][3]);
        }
}

// =============== fused Newton cooperative kernel (tensor cores) ===========
__device__ __forceinline__ void gbar(int target) {
    __syncthreads();
    if (threadIdx.x == 0) {
        __threadfence();
        atomicAdd(&g_cnt, 1);
        while (*(volatile int*)&g_cnt < target) __nanosleep(32);
    }
    __syncthreads();
}

// 64x64 output tile, K=256, bf16 hi/lo via mma.sync.
// mode 0: C=A@B^T(row-read)  1: C = 1.5*C - 0.5*res  2: C = sc*res
__device__ void mtile(const float* A, const float* B, float* C,
                      int bi, int bj, int mode, float sc,
                      __nv_bfloat16* AHI, __nv_bfloat16* ALO,
                      __nv_bfloat16* BHI, __nv_bfloat16* BLO) {
    const int tid = threadIdx.x, w = tid >> 5, lane = tid & 31;
    const int wm = w >> 2, wn = w & 3;          // warp tile 32m x 16n
    const int l4 = lane >> 2, q2 = (lane & 3) * 2;

    float acc[2][2][4];
#pragma unroll
    for (int i = 0; i < 2; i++)
#pragma unroll
        for (int j = 0; j < 2; j++)
#pragma unroll
            for (int r = 0; r < 4; r++) acc[i][j][r] = 0.f;

    for (int kc = 0; kc < 4; kc++) {
        const int k0g = kc * 64;
#pragma unroll
        for (int it = 0; it < 4; it++) {
            int e = it * 256 + tid;
            int row = e >> 4, f4 = e & 15;
            float4 va = __ldcg((const float4*)(A + (size_t)(bi + row) * C_DIM + k0g + f4 * 4));
            float4 vb = __ldcg((const float4*)(B + (size_t)(bj + row) * C_DIM + k0g + f4 * 4));
            __nv_bfloat16 h0, h1, h2, h3, l0, l1, l2, l3;
            split1(va.x, h0, l0); split1(va.y, h1, l1);
            split1(va.z, h2, l2); split1(va.w, h3, l3);
            *(uint2*)(AHI + row * PADK + f4 * 4) = make_uint2(packbf2(h0, h1), packbf2(h2, h3));
            *(uint2*)(ALO + row * PADK + f4 * 4) = make_uint2(packbf2(l0, l1), packbf2(l2, l3));
            split1(vb.x, h0, l0); split1(vb.y, h1, l1);
            split1(vb.z, h2, l2); split1(vb.w, h3, l3);
            *(uint2*)(BHI + row * PADK + f4 * 4) = make_uint2(packbf2(h0, h1), packbf2(h2, h3));
            *(uint2*)(BLO + row * PADK + f4 * 4) = make_uint2(packbf2(l0, l1), packbf2(l2, l3));
        }
        __syncthreads();
#pragma unroll
        for (int ks = 0; ks < 4; ks++) {
            const int k0 = ks * 16;
            uint32_t bh[2][2], bl[2][2];
#pragma unroll
            for (int nt = 0; nt < 2; nt++) {
                ldb(bh[nt], BHI, wn * 16 + nt * 8, k0, l4, q2);
                ldb(bl[nt], BLO, wn * 16 + nt * 8, k0, l4, q2);
            }
#pragma unroll
            for (int mt = 0; mt < 2; mt++) {
                uint32_t ah[4], al[4];
                lda(ah, AHI, wm * 32 + mt * 16, k0, l4, q2);
                lda(al, ALO, wm * 32 + mt * 16, k0, l4, q2);
#pragma unroll
                for (int nt = 0; nt < 2; nt++) {
                    mma_bf16(acc[mt][nt], ah, bh[nt]);
                    mma_bf16(acc[mt][nt], ah, bl[nt]);
                    mma_bf16(acc[mt][nt], al, bh[nt]);
                }
            }
        }
        __syncthreads();
    }

#pragma unroll
    for (int mt = 0; mt < 2; mt++)
#pragma unroll
        for (int nt = 0; nt < 2; nt++) {
            int gi = bi + wm * 32 + mt * 16 + l4;
            int gj = bj + wn * 16 + nt * 8 + q2;
            float r0 = acc[mt][nt][0], r1 = acc[mt][nt][1];
            float r2 = acc[mt][nt][2], r3 = acc[mt][nt][3];
            if (mode == 1) {
                r0 = 1.5f * __ldcg(&C[gi * C_DIM + gj]) - 0.5f * r0;
                r1 = 1.5f * __ldcg(&C[gi * C_DIM + gj + 1]) - 0.5f * r1;
                r2 = 1.5f * __ldcg(&C[(gi + 8) * C_DIM + gj]) - 0.5f * r2;
                r3 = 1.5f * __ldcg(&C[(gi + 8) * C_DIM + gj + 1]) - 0.5f * r3;
            } else if (mode == 2) {
                r0 *= sc; r1 *= sc; r2 *= sc; r3 *= sc;
            }
            *(float2*)(C + gi * C_DIM + gj) = make_float2(r0, r1);
            *(float2*)(C + (gi + 8) * C_DIM + gj) = make_float2(r2, r3);
        }
}

__global__ __launch_bounds__(256, 1) void newton_fused(const float* __restrict__ R) {
    const int cta = blockIdx.x, tid = threadIdx.x;
    __shared__ __align__(16) __nv_bfloat16 sAHI[64 * PADK];
    __shared__ __align__(16) __nv_bfloat16 sALO[64 * PADK];
    __shared__ __align__(16) __nv_bfloat16 sBHI[64 * PADK];
    __shared__ __align__(16) __nv_bfloat16 sBLO[64 * PADK];
    __shared__ float sh[256];
    int st = 0;

    // S0: gram reduce -> sigma (both symmetric halves). 1536 elems per CTA.
    for (int e = cta * 1536 + tid; e < (cta + 1) * 1536; e += 256) {
        int p = e >> 14, r = e & 16383;
        int i = r >> 7, j = r & 127;
        const float* src = g_part + (size_t)p * N_IMG * 16384 + r;
        float s = 0.f;
        for (int n = 0; n < N_IMG; n++) s += src[(size_t)n * 16384];
        int bi = (p == 2) ? 1 : 0, bj = (p == 0) ? 0 : 1;
        int gi = bi * 128 + i, gj = bj * 128 + j;
        float v = s * (1.0f / (float)M_TOT) - g_mean[gi] * g_mean[gj];
        if (gi == gj) v += EPSF;
        g_sigma[gi * C_DIM + gj] = v;
        g_sigma[gj * C_DIM + gi] = v;
    }
    gbar(++st * NCTA);

    // S1: trace (CTA 0)
    if (cta == 0) {
        sh[tid] = __ldcg(&g_sigma[tid * (C_DIM + 1)]);
        __syncthreads();
        for (int o = 128; o > 0; o >>= 1) {
            if (tid < o) sh[tid] += sh[tid + o];
            __syncthreads();
        }
        if (tid == 0) {
            float tr = 1.0f / sh[0];
            g_scal[0] = tr;
            g_scal[1] = sqrtf(tr);
        }
    }
    gbar(++st * NCTA);

    // S2: SN = sigma * tr_rec, P = I.  2048 per CTA.
    {
        float s0 = __ldcg(&g_scal[0]);
        for (int e = cta * 2048 + tid; e < (cta + 1) * 2048; e += 256) {
            int i = e >> 8, j = e & 255;
            g_SN[e] = __ldcg(&g_sigma[e]) * s0;
            g_P[e] = (i == j) ? 1.0f : 0.0f;
        }
    }
    gbar(++st * NCTA);

    // tile coords: 16 tiles of 64x64 per matrix
    const int t16 = cta & 15;
    const int bi = (t16 >> 2) * 64, bj = (t16 & 3) * 64;

    for (int it = 0; it < T_ITERS; it++) {
        // stage A: T = P@P (cta<16), QT = SN@P (cta>=16). P, SN symmetric.
        if (cta < 16)
            mtile(g_P, g_P, g_T, bi, bj, 0, 0.f, sAHI, sALO, sBHI, sBLO);
        else
            mtile(g_SN, g_P, g_QT, bi, bj, 0, 0.f, sAHI, sALO, sBHI, sBLO);
        gbar(++st * NCTA);
        // stage B: P = 1.5P - 0.5 * T@Q  (Q[k][j] = QT[j][k] row-read)
        if (cta < 16)
            mtile(g_T, g_QT, g_P, bi, bj, 1, 0.f, sAHI, sALO, sBHI, sBLO);
        gbar(++st * NCTA);
    }

    // M = sqrt(tr_rec) * R @ P  (P symmetric)
    if (cta < 16)
        mtile(R, g_P, g_M, bi, bj, 2, __ldcg(&g_scal[1]), sAHI, sALO, sBHI, sBLO);
    gbar(++st * NCTA);

    // msplit: 2048 per CTA
    for (int e = cta * 2048 + tid; e < (cta + 1) * 2048; e += 256) {
        float m = __ldcg(&g_M[e]);
        __nv_bfloat16 h = __float2bfloat16(m);
        g_Mhi[e] = h;
        g_Mlo[e] = __float2bfloat16(m - __bfloat162float(h));
    }
    // bvec: 8 rows per CTA
    for (int rr = 0; rr < 8; rr++) {
        int d = cta * 8 + rr;
        __syncthreads();
        sh[tid] = __ldcg(&g_M[d * C_DIM + tid]) * g_mean[tid];
        __syncthreads();
        for (int o = 128; o > 0; o >>= 1) {
            if (tid < o) sh[tid] += sh[tid + o];
            __syncthreads();
        }
        if (tid == 0) g_bvec[d] = sh[0];
    }
}

// ============== Out GEMM: both d-halves per CTA, X read once ==============
__global__ __launch_bounds__(256, 1)
void out_mma(const float* __restrict__ X, float* __restrict__ O) {
    extern __shared__ char sm[];
    const int mt = blockIdx.x, n = blockIdx.y;
    const int m0g = mt * 128;

    float* STG = (float*)sm;                               // 64 x 132 fp32
    __nv_bfloat16* A0HI = (__nv_bfloat16*)(sm + 33792);
    __nv_bfloat16* A0LO = A0HI + 128 * PADK;
    __nv_bfloat16* A1HI = A0LO + 128 * PADK;
    __nv_bfloat16* A1LO = A1HI + 128 * PADK;
    __nv_bfloat16* BHI  = A1LO + 128 * PADK;
    __nv_bfloat16* BLO  = BHI + 128 * PADK;

    const int tid = threadIdx.x, w = tid >> 5, lane = tid & 31;
    const int wd = w >> 2, wm = w & 3;
    const int l4 = lane >> 2, q2 = (lane & 3) * 2;

    float acc[2][4][4][4];
#pragma unroll
    for (int h = 0; h < 2; h++)
#pragma unroll
        for (int i = 0; i < 4; i++)
#pragma unroll
            for (int j = 0; j < 4; j++)
#pragma unroll
                for (int r = 0; r < 4; r++) acc[h][i][j][r] = 0.f;

    for (int cc = 0; cc < 4; cc++) {
        const int c0 = cc * 64;
#pragma unroll
        for (int it = 0; it < 8; it++) {
            int e = it * 256 + tid;
            int row = e >> 5, j4 = e & 31;
            float4 v = *(const float4*)(X + ((size_t)(n * C_DIM + c0 + row)) * HW + m0g + j4 * 4);
            *(float4*)(STG + row * 132 + j4 * 4) = v;
        }
#pragma unroll
        for (int dh = 0; dh < 2; dh++) {
            __nv_bfloat16* AH = dh ? A1HI : A0HI;
            __nv_bfloat16* AL = dh ? A1LO : A0LO;
#pragma unroll
            for (int it = 0; it < 8; it++) {
                int e = it * 256 + tid;
                int row = e >> 4, u = e & 15;
                *(uint2*)(AH + row * PADK + u * 4) =
                    *(const uint2*)(g_Mhi + (size_t)(dh * 128 + row) * C_DIM + c0 + u * 4);
                *(uint2*)(AL + row * PADK + u * 4) =
                    *(const uint2*)(g_Mlo + (size_t)(dh * 128 + row) * C_DIM + c0 + u * 4);
            }
        }
        __syncthreads();
        {
            int m = tid & 127, half = tid >> 7;
#pragma unroll
            for (int o = 0; o < 4; o++) {
                int ocg = half * 4 + o;
                float f[8];
#pragma unroll
                for (int kk = 0; kk < 8; kk++) f[kk] = STG[(ocg * 8 + kk) * 132 + m];
                __nv_bfloat16 h[8], l[8];
#pragma unroll
                for (int kk = 0; kk < 8; kk++) split1(f[kk], h[kk], l[kk]);
                *(uint4*)(BHI + m * PADK + ocg * 8) =
                    make_uint4(packbf2(h[0], h[1]), packbf2(h[2], h[3]),
                               packbf2(h[4], h[5]), packbf2(h[6], h[7]));
                *(uint4*)(BLO + m * PADK + ocg * 8) =
                    make_uint4(packbf2(l[0], l[1]), packbf2(l[2], l[3]),
                               packbf2(l[4], l[5]), packbf2(l[6], l[7]));
            }
        }
        __syncthreads();
#pragma unroll
        for (int ks = 0; ks < 4; ks++) {
            const int k0 = ks * 16;
            uint32_t bh[4][2], bl[4][2];
#pragma unroll
            for (int nt = 0; nt < 4; nt++) {
                ldb(bh[nt], BHI, wm * 32 + nt * 8, k0, l4, q2);
                ldb(bl[nt], BLO, wm * 32 + nt * 8, k0, l4, q2);
            }
#pragma unroll
            for (int dh = 0; dh < 2; dh++) {
                const __nv_bfloat16* AH = dh ? A1HI : A0HI;
                const __nv_bfloat16* AL = dh ? A1LO : A0LO;
#pragma unroll
                for (int dt = 0; dt < 4; dt++) {
                    uint32_t ah[4], al[4];
                    lda(ah, AH, wd * 64 + dt * 16, k0, l4, q2);
                    lda(al, AL, wd * 64 + dt * 16, k0, l4, q2);
#pragma unroll
                    for (int nt = 0; nt < 4; nt++) {
                        mma_bf16(acc[dh][dt][nt], ah, bh[nt]);
                        mma_bf16(acc[dh][dt][nt], ah, bl[nt]);
                        mma_bf16(acc[dh][dt][nt], al, bh[nt]);
                    }
                }
            }
        }
        __syncthreads();
    }

    float* obase = O + (size_t)n * C_DIM * HW;
#pragma unroll
    for (int dh = 0; dh < 2; dh++)
#pragma unroll
        for (int dt = 0; dt < 4; dt++) {
            int d = dh * 128 + wd * 64 + dt * 16 + l4;
            float b0 = g_bvec[d], b8 = g_bvec[d + 8];
#pragma unroll
            for (int nt = 0; nt < 4; nt++) {
                int m = m0g + wm * 32 + nt * 8 + q2;
                *(float2*)(obase + (size_t)d * HW + m) =
                    make_float2(acc[dh][dt][nt][0] - b0, acc[dh][dt][nt][1] - b0);
                *(float2*)(obase + (size_t)(d + 8) * HW + m) =
                    make_float2(acc[dh][dt][nt][2] - b8, acc[dh][dt][nt][3] - b8);
            }
        }
}

// ---------------- launcher ------------------------------------------------
extern "C" void kernel_launch(void* const* d_in, const int* in_sizes, int n_in,
                              void* d_out, int out_size) {
    (void)in_sizes; (void)n_in; (void)out_size;
    const float* X = (const float*)d_in[0];
    const float* R = (const float*)d_in[1];
    float* O = (float*)d_out;

    cudaFuncSetAttribute(gram_mma, cudaFuncAttributeMaxDynamicSharedMemorySize, 73728);
    cudaFuncSetAttribute(out_mma, cudaFuncAttributeMaxDynamicSharedMemorySize, 144384);

    reset_kernel<<<1, 1>>>();
    mean_kernel<<<C_DIM, 256>>>(X);
    gram_mma<<<dim3(3, N_IMG), 256, 73728>>>(X);
    newton_fused<<<NCTA, 256>>>(R);
    dummy_kernel<<<1, 1>>>();
    out_mma<<<dim3(8, N_IMG), 256, 144384>>>(X, O);
}

// round 15
// speedup vs baseline: 1.8917x; 1.0716x over previous
#include <cuda_runtime.h>
#include <cuda_bf16.h>
#include <stdint.h>
#include <math.h>

#define C_DIM 256
#define HW    1024
#define N_IMG 64
#define M_TOT (N_IMG * HW)
#define EPSF  1e-5f
#define PADK 72
#define NCTA 32

__device__ float g_part[(size_t)3 * N_IMG * 128 * 128];
__device__ float g_sigma[C_DIM * C_DIM];
__device__ float g_SN[C_DIM * C_DIM];
__device__ float g_P[C_DIM * C_DIM];
__device__ float g_T[C_DIM * C_DIM];
__device__ float g_QT[C_DIM * C_DIM];
__device__ float g_M[C_DIM * C_DIM];
__device__ __nv_bfloat16 g_Mhi[C_DIM * C_DIM];
__device__ __nv_bfloat16 g_Mlo[C_DIM * C_DIM];
__device__ float g_mean[C_DIM];
__device__ float g_bvec[C_DIM];
__device__ float g_scal[2];
__device__ int g_cnt;

// ======================= mma.sync helpers =================================
__device__ __forceinline__ void mma_bf16(float* c, const uint32_t* a, const uint32_t* b) {
    asm volatile(
        "mma.sync.aligned.m16n8k16.row.col.f32.bf16.bf16.f32 "
        "{%0,%1,%2,%3}, {%4,%5,%6,%7}, {%8,%9}, {%0,%1,%2,%3};"
        : "+f"(c[0]), "+f"(c[1]), "+f"(c[2]), "+f"(c[3])
        : "r"(a[0]), "r"(a[1]), "r"(a[2]), "r"(a[3]), "r"(b[0]), "r"(b[1]));
}
__device__ __forceinline__ uint32_t packbf2(__nv_bfloat16 a, __nv_bfloat16 b) {
    return (uint32_t)__bfloat16_as_ushort(a) | ((uint32_t)__bfloat16_as_ushort(b) << 16);
}
__device__ __forceinline__ void split1(float x, __nv_bfloat16& h, __nv_bfloat16& l) {
    h = __float2bfloat16(x);
    l = __float2bfloat16(x - __bfloat162float(h));
}
__device__ __forceinline__ void cvt4(const float4& v, void* hp, void* lp) {
    __nv_bfloat16 h0, h1, h2, h3, l0, l1, l2, l3;
    split1(v.x, h0, l0); split1(v.y, h1, l1);
    split1(v.z, h2, l2); split1(v.w, h3, l3);
    *(uint2*)hp = make_uint2(packbf2(h0, h1), packbf2(h2, h3));
    *(uint2*)lp = make_uint2(packbf2(l0, l1), packbf2(l2, l3));
}
__device__ __forceinline__ void lda(uint32_t* a, const __nv_bfloat16* t,
                                    int row, int k, int l4, int q2) {
    const __nv_bfloat16* p = t + (row + l4) * PADK + k + q2;
    a[0] = *(const uint32_t*)p;
    a[1] = *(const uint32_t*)(p + 8 * PADK);
    a[2] = *(const uint32_t*)(p + 8);
    a[3] = *(const uint32_t*)(p + 8 * PADK + 8);
}
__device__ __forceinline__ void ldb(uint32_t* b, const __nv_bfloat16* t,
                                    int n, int k, int l4, int q2) {
    const __nv_bfloat16* p = t + (n + l4) * PADK + k + q2;
    b[0] = *(const uint32_t*)p;
    b[1] = *(const uint32_t*)(p + 8);
}

__global__ void reset_kernel() { g_cnt = 0; }

// ---------------- per-channel mean --------------------------------------
__global__ void mean_kernel(const float* __restrict__ X) {
    int c = blockIdx.x, t = threadIdx.x;
    float s = 0.f;
    for (int n = 0; n < N_IMG; n++) {
        const float* p = X + ((size_t)(n * C_DIM + c)) * HW;
        for (int s0 = t; s0 < HW; s0 += 256) s += p[s0];
    }
    __shared__ float sh[256];
    sh[t] = s;
    __syncthreads();
    for (int o = 128; o > 0; o >>= 1) {
        if (t < o) sh[t] += sh[t + o];
        __syncthreads();
    }
    if (t == 0) g_mean[c] = sh[0] * (1.0f / (float)M_TOT);
}

// ================= Gram via mma.sync (proven path) ========================
__global__ __launch_bounds__(256, 1)
void gram_mma(const float* __restrict__ X) {
    extern __shared__ char sm[];
    const int p = blockIdx.x, n = blockIdx.y;
    const int bi = (p == 2) ? 1 : 0;
    const int bj = (p == 0) ? 0 : 1;
    const bool diag = (bi == bj);

    __nv_bfloat16* AHI = (__nv_bfloat16*)sm;
    __nv_bfloat16* ALO = AHI + 128 * PADK;
    __nv_bfloat16* BHI = ALO + 128 * PADK;
    __nv_bfloat16* BLO = BHI + 128 * PADK;

    const int tid = threadIdx.x, w = tid >> 5, lane = tid & 31;
    const int wm = w >> 2, wn = w & 3;
    const int l4 = lane >> 2, q2 = (lane & 3) * 2;

    float acc[4][4][4];
#pragma unroll
    for (int i = 0; i < 4; i++)
#pragma unroll
        for (int j = 0; j < 4; j++)
#pragma unroll
            for (int r = 0; r < 4; r++) acc[i][j][r] = 0.f;

    const __nv_bfloat16* Bh = diag ? AHI : BHI;
    const __nv_bfloat16* Bl = diag ? ALO : BLO;

    for (int kc = 0; kc < 16; kc++) {
        const int k0g = kc * 64;
        float4 va[8], vb[8];
#pragma unroll
        for (int it = 0; it < 8; it++) {
            int e = it * 256 + tid;
            int row = e >> 4, f4 = e & 15;
            va[it] = *(const float4*)(X + ((size_t)(n * C_DIM + bi * 128 + row)) * HW + k0g + f4 * 4);
        }
        if (!diag)
#pragma unroll
            for (int it = 0; it < 8; it++) {
                int e = it * 256 + tid;
                int row = e >> 4, f4 = e & 15;
                vb[it] = *(const float4*)(X + ((size_t)(n * C_DIM + bj * 128 + row)) * HW + k0g + f4 * 4);
            }
#pragma unroll
        for (int it = 0; it < 8; it++) {
            int e = it * 256 + tid;
            int row = e >> 4, f4 = e & 15;
            cvt4(va[it], AHI + row * PADK + f4 * 4, ALO + row * PADK + f4 * 4);
        }
        if (!diag)
#pragma unroll
            for (int it = 0; it < 8; it++) {
                int e = it * 256 + tid;
                int row = e >> 4, f4 = e & 15;
                cvt4(vb[it], BHI + row * PADK + f4 * 4, BLO + row * PADK + f4 * 4);
            }
        __syncthreads();
#pragma unroll
        for (int ks = 0; ks < 4; ks++) {
            const int k0 = ks * 16;
            uint32_t bh[4][2], bl[4][2];
#pragma unroll
            for (int nt = 0; nt < 4; nt++) {
                ldb(bh[nt], Bh, wn * 32 + nt * 8, k0, l4, q2);
                ldb(bl[nt], Bl, wn * 32 + nt * 8, k0, l4, q2);
            }
#pragma unroll
            for (int mt = 0; mt < 4; mt++) {
                uint32_t ah[4], al[4];
                lda(ah, AHI, wm * 64 + mt * 16, k0, l4, q2);
                lda(al, ALO, wm * 64 + mt * 16, k0, l4, q2);
#pragma unroll
                for (int nt = 0; nt < 4; nt++) {
                    mma_bf16(acc[mt][nt], ah, bh[nt]);
                    mma_bf16(acc[mt][nt], ah, bl[nt]);
                    mma_bf16(acc[mt][nt], al, bh[nt]);
                }
            }
        }
        __syncthreads();
    }

    float* outp = g_part + ((size_t)p * N_IMG + n) * 16384;
#pragma unroll
    for (int mt = 0; mt < 4; mt++)
#pragma unroll
        for (int nt = 0; nt < 4; nt++) {
            int i0 = wm * 64 + mt * 16 + l4;
            int j0 = wn * 32 + nt * 8 + q2;
            *(float2*)(outp + i0 * 128 + j0) = make_float2(acc[mt][nt][0], acc[mt][nt][1]);
            *(float2*)(outp + (i0 + 8) * 128 + j0) = make_float2(acc[mt][nt][2], acc[mt][nt][3]);
        }
}

// ============== wide partial-reduce + Sigma build =========================
// grid (3, 128), block 128
__global__ void sigma_reduce() {
    const int p = blockIdx.x, i = blockIdx.y, j = threadIdx.x;
    const int bi = (p == 2) ? 1 : 0;
    const int bj = (p == 0) ? 0 : 1;
    const float* src = g_part + (size_t)p * N_IMG * 16384 + i * 128 + j;
    float s = 0.f;
#pragma unroll 8
    for (int n = 0; n < N_IMG; n++) s += src[(size_t)n * 16384];
    int gi = bi * 128 + i, gj = bj * 128 + j;
    float v = s * (1.0f / (float)M_TOT) - g_mean[gi] * g_mean[gj];
    if (gi == gj) v += EPSF;
    g_sigma[gi * C_DIM + gj] = v;
    g_sigma[gj * C_DIM + gi] = v;
}

// =============== fused Newton cooperative kernel (tensor cores) ===========
__device__ __forceinline__ void gbar(int target) {
    __syncthreads();
    if (threadIdx.x == 0) {
        __threadfence();
        atomicAdd(&g_cnt, 1);
        while (*(volatile int*)&g_cnt < target) __nanosleep(32);
    }
    __syncthreads();
}

// 64x64 tile, K=256. mode 0: C = A@B^T(row-read)
__device__ void mtile(const float* A, const float* B, float* C, int bi, int bj,
                      __nv_bfloat16* AHI, __nv_bfloat16* ALO,
                      __nv_bfloat16* BHI, __nv_bfloat16* BLO) {
    const int tid = threadIdx.x, w = tid >> 5, lane = tid & 31;
    const int wm = w >> 2, wn = w & 3;
    const int l4 = lane >> 2, q2 = (lane & 3) * 2;

    float acc[2][2][4];
#pragma unroll
    for (int i = 0; i < 2; i++)
#pragma unroll
        for (int j = 0; j < 2; j++)
#pragma unroll
            for (int r = 0; r < 4; r++) acc[i][j][r] = 0.f;

    for (int kc = 0; kc < 4; kc++) {
        const int k0g = kc * 64;
        float4 va[4], vb[4];
#pragma unroll
        for (int it = 0; it < 4; it++) {
            int e = it * 256 + tid;
            int row = e >> 4, f4 = e & 15;
            va[it] = __ldcg((const float4*)(A + (size_t)(bi + row) * C_DIM + k0g + f4 * 4));
            vb[it] = __ldcg((const float4*)(B + (size_t)(bj + row) * C_DIM + k0g + f4 * 4));
        }
#pragma unroll
        for (int it = 0; it < 4; it++) {
            int e = it * 256 + tid;
            int row = e >> 4, f4 = e & 15;
            cvt4(va[it], AHI + row * PADK + f4 * 4, ALO + row * PADK + f4 * 4);
            cvt4(vb[it], BHI + row * PADK + f4 * 4, BLO + row * PADK + f4 * 4);
        }
        __syncthreads();
#pragma unroll
        for (int ks = 0; ks < 4; ks++) {
            const int k0 = ks * 16;
            uint32_t bh[2][2], bl[2][2];
#pragma unroll
            for (int nt = 0; nt < 2; nt++) {
                ldb(bh[nt], BHI, wn * 16 + nt * 8, k0, l4, q2);
                ldb(bl[nt], BLO, wn * 16 + nt * 8, k0, l4, q2);
            }
#pragma unroll
            for (int mt = 0; mt < 2; mt++) {
                uint32_t ah[4], al[4];
                lda(ah, AHI, wm * 32 + mt * 16, k0, l4, q2);
                lda(al, ALO, wm * 32 + mt * 16, k0, l4, q2);
#pragma unroll
                for (int nt = 0; nt < 2; nt++) {
                    mma_bf16(acc[mt][nt], ah, bh[nt]);
                    mma_bf16(acc[mt][nt], ah, bl[nt]);
                    mma_bf16(acc[mt][nt], al, bh[nt]);
                }
            }
        }
        __syncthreads();
    }

#pragma unroll
    for (int mt = 0; mt < 2; mt++)
#pragma unroll
        for (int nt = 0; nt < 2; nt++) {
            int gi = bi + wm * 32 + mt * 16 + l4;
            int gj = bj + wn * 16 + nt * 8 + q2;
            *(float2*)(C + gi * C_DIM + gj) = make_float2(acc[mt][nt][0], acc[mt][nt][1]);
            *(float2*)(C + (gi + 8) * C_DIM + gj) = make_float2(acc[mt][nt][2], acc[mt][nt][3]);
        }
}

// 64x32 tile, K=256, all-CTA stages. mode 1: C=1.5C-0.5res  2: C=sc*res
__device__ void mtile32(const float* A, const float* B, float* C, int bi, int bj,
                        int mode, float sc,
                        __nv_bfloat16* AHI, __nv_bfloat16* ALO,
                        __nv_bfloat16* BHI, __nv_bfloat16* BLO) {
    const int tid = threadIdx.x, w = tid >> 5, lane = tid & 31;
    const int wm = w >> 1, wn = w & 1;          // 4x2 warps, 16m x 16n each
    const int l4 = lane >> 2, q2 = (lane & 3) * 2;

    float acc[2][4];
#pragma unroll
    for (int j = 0; j < 2; j++)
#pragma unroll
        for (int r = 0; r < 4; r++) acc[j][r] = 0.f;

    for (int kc = 0; kc < 4; kc++) {
        const int k0g = kc * 64;
        float4 va[4], vb[2];
#pragma unroll
        for (int it = 0; it < 4; it++) {
            int e = it * 256 + tid;
            int row = e >> 4, f4 = e & 15;
            va[it] = __ldcg((const float4*)(A + (size_t)(bi + row) * C_DIM + k0g + f4 * 4));
        }
#pragma unroll
        for (int it = 0; it < 2; it++) {
            int e = it * 256 + tid;
            int row = e >> 4, f4 = e & 15;
            vb[it] = __ldcg((const float4*)(B + (size_t)(bj + row) * C_DIM + k0g + f4 * 4));
        }
#pragma unroll
        for (int it = 0; it < 4; it++) {
            int e = it * 256 + tid;
            int row = e >> 4, f4 = e & 15;
            cvt4(va[it], AHI + row * PADK + f4 * 4, ALO + row * PADK + f4 * 4);
        }
#pragma unroll
        for (int it = 0; it < 2; it++) {
            int e = it * 256 + tid;
            int row = e >> 4, f4 = e & 15;
            cvt4(vb[it], BHI + row * PADK + f4 * 4, BLO + row * PADK + f4 * 4);
        }
        __syncthreads();
#pragma unroll
        for (int ks = 0; ks < 4; ks++) {
            const int k0 = ks * 16;
            uint32_t ah[4], al[4];
            lda(ah, AHI, wm * 16, k0, l4, q2);
            lda(al, ALO, wm * 16, k0, l4, q2);
#pragma unroll
            for (int nt = 0; nt < 2; nt++) {
                uint32_t bh[2], bl[2];
                ldb(bh, BHI, wn * 16 + nt * 8, k0, l4, q2);
                ldb(bl, BLO, wn * 16 + nt * 8, k0, l4, q2);
                mma_bf16(acc[nt], ah, bh);
                mma_bf16(acc[nt], ah, bl);
                mma_bf16(acc[nt], al, bh);
            }
        }
        __syncthreads();
    }

#pragma unroll
    for (int nt = 0; nt < 2; nt++) {
        int gi = bi + wm * 16 + l4;
        int gj = bj + wn * 16 + nt * 8 + q2;
        float r0 = acc[nt][0], r1 = acc[nt][1], r2 = acc[nt][2], r3 = acc[nt][3];
        if (mode == 1) {
            float2 cA = __ldcg((const float2*)(C + gi * C_DIM + gj));
            float2 cB = __ldcg((const float2*)(C + (gi + 8) * C_DIM + gj));
            r0 = 1.5f * cA.x - 0.5f * r0;
            r1 = 1.5f * cA.y - 0.5f * r1;
            r2 = 1.5f * cB.x - 0.5f * r2;
            r3 = 1.5f * cB.y - 0.5f * r3;
        } else if (mode == 2) {
            r0 *= sc; r1 *= sc; r2 *= sc; r3 *= sc;
        }
        *(float2*)(C + gi * C_DIM + gj) = make_float2(r0, r1);
        *(float2*)(C + (gi + 8) * C_DIM + gj) = make_float2(r2, r3);
    }
}

__global__ __launch_bounds__(256, 1) void newton_fused(const float* __restrict__ R) {
    const int cta = blockIdx.x, tid = threadIdx.x;
    __shared__ __align__(16) __nv_bfloat16 sAHI[64 * PADK];
    __shared__ __align__(16) __nv_bfloat16 sALO[64 * PADK];
    __shared__ __align__(16) __nv_bfloat16 sBHI[64 * PADK];
    __shared__ __align__(16) __nv_bfloat16 sBLO[64 * PADK];
    __shared__ float sh[256];
    int st = 0;

    // trace (CTA 0); sigma was written by a prior launch -> plain loads OK
    if (cta == 0) {
        sh[tid] = g_sigma[tid * (C_DIM + 1)];
        __syncthreads();
        for (int o = 128; o > 0; o >>= 1) {
            if (tid < o) sh[tid] += sh[tid + o];
            __syncthreads();
        }
        if (tid == 0) {
            float tr = 1.0f / sh[0];
            g_scal[0] = tr;
            g_scal[1] = sqrtf(tr);
        }
    }
    gbar(++st * NCTA);

    // SN = sigma*tr ; P1 = 1.5 I - 0.5 SN  (iteration 0 done analytically)
    {
        float s0 = __ldcg(&g_scal[0]);
        for (int e = cta * 2048 + tid; e < (cta + 1) * 2048; e += 256) {
            int i = e >> 8, j = e & 255;
            float sn = g_sigma[e] * s0;
            g_SN[e] = sn;
            g_P[e] = ((i == j) ? 1.5f : 0.0f) - 0.5f * sn;
        }
    }
    gbar(++st * NCTA);

    const int t16 = cta & 15;
    const int bi64 = (t16 >> 2) * 64, bj64 = (t16 & 3) * 64;
    const int bi32 = (cta >> 3) * 64, bj32 = (cta & 7) * 32;

    for (int it = 0; it < 9; it++) {
        if (cta < 16)
            mtile(g_P, g_P, g_T, bi64, bj64, sAHI, sALO, sBHI, sBLO);
        else
            mtile(g_SN, g_P, g_QT, bi64, bj64, sAHI, sALO, sBHI, sBLO);
        gbar(++st * NCTA);
        mtile32(g_T, g_QT, g_P, bi32, bj32, 1, 0.f, sAHI, sALO, sBHI, sBLO);
        gbar(++st * NCTA);
    }

    // M = sqrt(tr_rec) * R @ P  (P symmetric row-read)
    mtile32(R, g_P, g_M, bi32, bj32, 2, __ldcg(&g_scal[1]), sAHI, sALO, sBHI, sBLO);
    gbar(++st * NCTA);

    // msplit
    for (int e = cta * 2048 + tid; e < (cta + 1) * 2048; e += 256) {
        float m = __ldcg(&g_M[e]);
        __nv_bfloat16 h = __float2bfloat16(m);
        g_Mhi[e] = h;
        g_Mlo[e] = __float2bfloat16(m - __bfloat162float(h));
    }
    // bvec: 8 rows per CTA
    for (int rr = 0; rr < 8; rr++) {
        int d = cta * 8 + rr;
        __syncthreads();
        sh[tid] = __ldcg(&g_M[d * C_DIM + tid]) * g_mean[tid];
        __syncthreads();
        for (int o = 128; o > 0; o >>= 1) {
            if (tid < o) sh[tid] += sh[tid + o];
            __syncthreads();
        }
        if (tid == 0) g_bvec[d] = sh[0];
    }
}

// ============== Out GEMM: both d-halves per CTA, X read once ==============
__global__ __launch_bounds__(256, 1)
void out_mma(const float* __restrict__ X, float* __restrict__ O) {
    extern __shared__ char sm[];
    const int mt = blockIdx.x, n = blockIdx.y;
    const int m0g = mt * 128;

    float* STG = (float*)sm;                               // 64 x 132 fp32
    __nv_bfloat16* A0HI = (__nv_bfloat16*)(sm + 33792);
    __nv_bfloat16* A0LO = A0HI + 128 * PADK;
    __nv_bfloat16* A1HI = A0LO + 128 * PADK;
    __nv_bfloat16* A1LO = A1HI + 128 * PADK;
    __nv_bfloat16* BHI  = A1LO + 128 * PADK;
    __nv_bfloat16* BLO  = BHI + 128 * PADK;

    const int tid = threadIdx.x, w = tid >> 5, lane = tid & 31;
    const int wd = w >> 2, wm = w & 3;
    const int l4 = lane >> 2, q2 = (lane & 3) * 2;

    float acc[2][4][4][4];
#pragma unroll
    for (int h = 0; h < 2; h++)
#pragma unroll
        for (int i = 0; i < 4; i++)
#pragma unroll
            for (int j = 0; j < 4; j++)
#pragma unroll
                for (int r = 0; r < 4; r++) acc[h][i][j][r] = 0.f;

    for (int cc = 0; cc < 4; cc++) {
        const int c0 = cc * 64;
#pragma unroll
        for (int it = 0; it < 8; it++) {
            int e = it * 256 + tid;
            int row = e >> 5, j4 = e & 31;
            float4 v = *(const float4*)(X + ((size_t)(n * C_DIM + c0 + row)) * HW + m0g + j4 * 4);
            *(float4*)(STG + row * 132 + j4 * 4) = v;
        }
#pragma unroll
        for (int dh = 0; dh < 2; dh++) {
            __nv_bfloat16* AH = dh ? A1HI : A0HI;
            __nv_bfloat16* AL = dh ? A1LO : A0LO;
#pragma unroll
            for (int it = 0; it < 8; it++) {
                int e = it * 256 + tid;
                int row = e >> 4, u = e & 15;
                *(uint2*)(AH + row * PADK + u * 4) =
                    *(const uint2*)(g_Mhi + (size_t)(dh * 128 + row) * C_DIM + c0 + u * 4);
                *(uint2*)(AL + row * PADK + u * 4) =
                    *(const uint2*)(g_Mlo + (size_t)(dh * 128 + row) * C_DIM + c0 + u * 4);
            }
        }
        __syncthreads();
        {
            int m = tid & 127, half = tid >> 7;
#pragma unroll
            for (int o = 0; o < 4; o++) {
                int ocg = half * 4 + o;
                float f[8];
#pragma unroll
                for (int kk = 0; kk < 8; kk++) f[kk] = STG[(ocg * 8 + kk) * 132 + m];
                __nv_bfloat16 h[8], l[8];
#pragma unroll
                for (int kk = 0; kk < 8; kk++) split1(f[kk], h[kk], l[kk]);
                *(uint4*)(BHI + m * PADK + ocg * 8) =
                    make_uint4(packbf2(h[0], h[1]), packbf2(h[2], h[3]),
                               packbf2(h[4], h[5]), packbf2(h[6], h[7]));
                *(uint4*)(BLO + m * PADK + ocg * 8) =
                    make_uint4(packbf2(l[0], l[1]), packbf2(l[2], l[3]),
                               packbf2(l[4], l[5]), packbf2(l[6], l[7]));
            }
        }
        __syncthreads();
#pragma unroll
        for (int ks = 0; ks < 4; ks++) {
            const int k0 = ks * 16;
            uint32_t bh[4][2], bl[4][2];
#pragma unroll
            for (int nt = 0; nt < 4; nt++) {
                ldb(bh[nt], BHI, wm * 32 + nt * 8, k0, l4, q2);
                ldb(bl[nt], BLO, wm * 32 + nt * 8, k0, l4, q2);
            }
#pragma unroll
            for (int dh = 0; dh < 2; dh++) {
                const __nv_bfloat16* AH = dh ? A1HI : A0HI;
                const __nv_bfloat16* AL = dh ? A1LO : A0LO;
#pragma unroll
                for (int dt = 0; dt < 4; dt++) {
                    uint32_t ah[4], al[4];
                    lda(ah, AH, wd * 64 + dt * 16, k0, l4, q2);
                    lda(al, AL, wd * 64 + dt * 16, k0, l4, q2);
#pragma unroll
                    for (int nt = 0; nt < 4; nt++) {
                        mma_bf16(acc[dh][dt][nt], ah, bh[nt]);
                        mma_bf16(acc[dh][dt][nt], ah, bl[nt]);
                        mma_bf16(acc[dh][dt][nt], al, bh[nt]);
                    }
                }
            }
        }
        __syncthreads();
    }

    float* obase = O + (size_t)n * C_DIM * HW;
#pragma unroll
    for (int dh = 0; dh < 2; dh++)
#pragma unroll
        for (int dt = 0; dt < 4; dt++) {
            int d = dh * 128 + wd * 64 + dt * 16 + l4;
            float b0 = g_bvec[d], b8 = g_bvec[d + 8];
#pragma unroll
            for (int nt = 0; nt < 4; nt++) {
                int m = m0g + wm * 32 + nt * 8 + q2;
                *(float2*)(obase + (size_t)d * HW + m) =
                    make_float2(acc[dh][dt][nt][0] - b0, acc[dh][dt][nt][1] - b0);
                *(float2*)(obase + (size_t)(d + 8) * HW + m) =
                    make_float2(acc[dh][dt][nt][2] - b8, acc[dh][dt][nt][3] - b8);
            }
        }
}

// ---------------- launcher ------------------------------------------------
extern "C" void kernel_launch(void* const* d_in, const int* in_sizes, int n_in,
                              void* d_out, int out_size) {
    (void)in_sizes; (void)n_in; (void)out_size;
    const float* X = (const float*)d_in[0];
    const float* R = (const float*)d_in[1];
    float* O = (float*)d_out;

    cudaFuncSetAttribute(gram_mma, cudaFuncAttributeMaxDynamicSharedMemorySize, 73728);
    cudaFuncSetAttribute(out_mma, cudaFuncAttributeMaxDynamicSharedMemorySize, 144384);

    reset_kernel<<<1, 1>>>();
    mean_kernel<<<C_DIM, 256>>>(X);
    gram_mma<<<dim3(3, N_IMG), 256, 73728>>>(X);
    sigma_reduce<<<dim3(3, 128), 128>>>();
    newton_fused<<<NCTA, 256>>>(R);
    out_mma<<<dim3(8, N_IMG), 256, 144384>>>(X, O);
}

// round 16
// speedup vs baseline: 2.4939x; 1.3183x over previous
#include <cuda_runtime.h>
#include <cuda_bf16.h>
#include <stdint.h>
#include <math.h>

#define C_DIM 256
#define HW    1024
#define N_IMG 64
#define M_TOT (N_IMG * HW)
#define EPSF  1e-5f
#define PADK 72
#define NCTA 32

__device__ float g_part[(size_t)3 * N_IMG * 128 * 128];
__device__ float g_msum[N_IMG * C_DIM];
__device__ float g_sigma[C_DIM * C_DIM];
__device__ float g_SN[C_DIM * C_DIM];
__device__ float g_P[C_DIM * C_DIM];
__device__ float g_T[C_DIM * C_DIM];
__device__ float g_QT[C_DIM * C_DIM];
__device__ float g_M[C_DIM * C_DIM];
__device__ __nv_bfloat16 g_Mhi[C_DIM * C_DIM];
__device__ __nv_bfloat16 g_Mlo[C_DIM * C_DIM];
__device__ float g_mean[C_DIM];
__device__ float g_bvec[C_DIM];
__device__ float g_scal[2];
__device__ int g_cnt;

// ======================= mma.sync helpers =================================
__device__ __forceinline__ void mma_bf16(float* c, const uint32_t* a, const uint32_t* b) {
    asm volatile(
        "mma.sync.aligned.m16n8k16.row.col.f32.bf16.bf16.f32 "
        "{%0,%1,%2,%3}, {%4,%5,%6,%7}, {%8,%9}, {%0,%1,%2,%3};"
        : "+f"(c[0]), "+f"(c[1]), "+f"(c[2]), "+f"(c[3])
        : "r"(a[0]), "r"(a[1]), "r"(a[2]), "r"(a[3]), "r"(b[0]), "r"(b[1]));
}
__device__ __forceinline__ uint32_t packbf2(__nv_bfloat16 a, __nv_bfloat16 b) {
    return (uint32_t)__bfloat16_as_ushort(a) | ((uint32_t)__bfloat16_as_ushort(b) << 16);
}
__device__ __forceinline__ void split1(float x, __nv_bfloat16& h, __nv_bfloat16& l) {
    h = __float2bfloat16(x);
    l = __float2bfloat16(x - __bfloat162float(h));
}
__device__ __forceinline__ void cvt4(const float4& v, void* hp, void* lp) {
    __nv_bfloat16 h0, h1, h2, h3, l0, l1, l2, l3;
    split1(v.x, h0, l0); split1(v.y, h1, l1);
    split1(v.z, h2, l2); split1(v.w, h3, l3);
    *(uint2*)hp = make_uint2(packbf2(h0, h1), packbf2(h2, h3));
    *(uint2*)lp = make_uint2(packbf2(l0, l1), packbf2(l2, l3));
}
__device__ __forceinline__ void lda(uint32_t* a, const __nv_bfloat16* t,
                                    int row, int k, int l4, int q2) {
    const __nv_bfloat16* p = t + (row + l4) * PADK + k + q2;
    a[0] = *(const uint32_t*)p;
    a[1] = *(const uint32_t*)(p + 8 * PADK);
    a[2] = *(const uint32_t*)(p + 8);
    a[3] = *(const uint32_t*)(p + 8 * PADK + 8);
}
__device__ __forceinline__ void ldb(uint32_t* b, const __nv_bfloat16* t,
                                    int n, int k, int l4, int q2) {
    const __nv_bfloat16* p = t + (n + l4) * PADK + k + q2;
    b[0] = *(const uint32_t*)p;
    b[1] = *(const uint32_t*)(p + 8);
}

__global__ void reset_kernel() { g_cnt = 0; }

// ================= Gram via mma.sync + fused mean partials ================
// grid (3 pairs, 64 images), 2 CTAs/SM co-residency.
__global__ __launch_bounds__(256, 2)
void gram_mma(const float* __restrict__ X) {
    extern __shared__ char sm[];
    const int p = blockIdx.x, n = blockIdx.y;
    const int bi = (p == 2) ? 1 : 0;
    const int bj = (p == 0) ? 0 : 1;
    const bool diag = (bi == bj);

    __nv_bfloat16* AHI = (__nv_bfloat16*)sm;
    __nv_bfloat16* ALO = AHI + 128 * PADK;
    __nv_bfloat16* BHI = ALO + 128 * PADK;
    __nv_bfloat16* BLO = BHI + 128 * PADK;

    const int tid = threadIdx.x, w = tid >> 5, lane = tid & 31;
    const int wm = w >> 2, wn = w & 3;
    const int l4 = lane >> 2, q2 = (lane & 3) * 2;

    float acc[4][4][4];
#pragma unroll
    for (int i = 0; i < 4; i++)
#pragma unroll
        for (int j = 0; j < 4; j++)
#pragma unroll
            for (int r = 0; r < 4; r++) acc[i][j][r] = 0.f;

    float srow[8];
#pragma unroll
    for (int i = 0; i < 8; i++) srow[i] = 0.f;

    const __nv_bfloat16* Bh = diag ? AHI : BHI;
    const __nv_bfloat16* Bl = diag ? ALO : BLO;

    for (int kc = 0; kc < 16; kc++) {
        const int k0g = kc * 64;
        float4 v[4];
#pragma unroll
        for (int hb = 0; hb < 2; hb++) {
#pragma unroll
            for (int it = 0; it < 4; it++) {
                int e = (hb * 4 + it) * 256 + tid;
                int row = e >> 4, f4 = e & 15;
                v[it] = *(const float4*)(X + ((size_t)(n * C_DIM + bi * 128 + row)) * HW + k0g + f4 * 4);
            }
            if (diag)
#pragma unroll
                for (int it = 0; it < 4; it++)
                    srow[hb * 4 + it] += v[it].x + v[it].y + v[it].z + v[it].w;
#pragma unroll
            for (int it = 0; it < 4; it++) {
                int e = (hb * 4 + it) * 256 + tid;
                int row = e >> 4, f4 = e & 15;
                cvt4(v[it], AHI + row * PADK + f4 * 4, ALO + row * PADK + f4 * 4);
            }
        }
        if (!diag) {
#pragma unroll
            for (int hb = 0; hb < 2; hb++) {
#pragma unroll
                for (int it = 0; it < 4; it++) {
                    int e = (hb * 4 + it) * 256 + tid;
                    int row = e >> 4, f4 = e & 15;
                    v[it] = *(const float4*)(X + ((size_t)(n * C_DIM + bj * 128 + row)) * HW + k0g + f4 * 4);
                }
#pragma unroll
                for (int it = 0; it < 4; it++) {
                    int e = (hb * 4 + it) * 256 + tid;
                    int row = e >> 4, f4 = e & 15;
                    cvt4(v[it], BHI + row * PADK + f4 * 4, BLO + row * PADK + f4 * 4);
                }
            }
        }
        __syncthreads();
#pragma unroll
        for (int ks = 0; ks < 4; ks++) {
            const int k0 = ks * 16;
            uint32_t bh[4][2], bl[4][2];
#pragma unroll
            for (int nt = 0; nt < 4; nt++) {
                ldb(bh[nt], Bh, wn * 32 + nt * 8, k0, l4, q2);
                ldb(bl[nt], Bl, wn * 32 + nt * 8, k0, l4, q2);
            }
#pragma unroll
            for (int mt = 0; mt < 4; mt++) {
                uint32_t ah[4], al[4];
                lda(ah, AHI, wm * 64 + mt * 16, k0, l4, q2);
                lda(al, ALO, wm * 64 + mt * 16, k0, l4, q2);
#pragma unroll
                for (int nt = 0; nt < 4; nt++) {
                    mma_bf16(acc[mt][nt], ah, bh[nt]);
                    mma_bf16(acc[mt][nt], ah, bl[nt]);
                    mma_bf16(acc[mt][nt], al, bh[nt]);
                }
            }
        }
        __syncthreads();
    }

    if (diag) {
#pragma unroll
        for (int it = 0; it < 8; it++) {
            float sv = srow[it];
            sv += __shfl_xor_sync(0xffffffffu, sv, 1);
            sv += __shfl_xor_sync(0xffffffffu, sv, 2);
            sv += __shfl_xor_sync(0xffffffffu, sv, 4);
            sv += __shfl_xor_sync(0xffffffffu, sv, 8);
            if ((tid & 15) == 0)
                g_msum[n * C_DIM + bi * 128 + it * 16 + (tid >> 4)] = sv;
        }
    }

    float* outp = g_part + ((size_t)p * N_IMG + n) * 16384;
#pragma unroll
    for (int mt = 0; mt < 4; mt++)
#pragma unroll
        for (int nt = 0; nt < 4; nt++) {
            int i0 = wm * 64 + mt * 16 + l4;
            int j0 = wn * 32 + nt * 8 + q2;
            *(float2*)(outp + i0 * 128 + j0) = make_float2(acc[mt][nt][0], acc[mt][nt][1]);
            *(float2*)(outp + (i0 + 8) * 128 + j0) = make_float2(acc[mt][nt][2], acc[mt][nt][3]);
        }
}

// ---------------- fold per-image mean partials ---------------------------
__global__ void meanp_kernel() {
    int c = threadIdx.x;
    float s = 0.f;
#pragma unroll 8
    for (int n = 0; n < N_IMG; n++) s += g_msum[n * C_DIM + c];
    g_mean[c] = s * (1.0f / (float)M_TOT);
}

// ============== wide partial-reduce + Sigma build =========================
__global__ void sigma_reduce() {
    const int p = blockIdx.x, i = blockIdx.y, j = threadIdx.x;
    const int bi = (p == 2) ? 1 : 0;
    const int bj = (p == 0) ? 0 : 1;
    const float* src = g_part + (size_t)p * N_IMG * 16384 + i * 128 + j;
    float s = 0.f;
#pragma unroll 8
    for (int n = 0; n < N_IMG; n++) s += src[(size_t)n * 16384];
    int gi = bi * 128 + i, gj = bj * 128 + j;
    float v = s * (1.0f / (float)M_TOT) - g_mean[gi] * g_mean[gj];
    if (gi == gj) v += EPSF;
    g_sigma[gi * C_DIM + gj] = v;
    g_sigma[gj * C_DIM + gi] = v;
}

// =============== fused Newton cooperative kernel (tensor cores) ===========
__device__ __forceinline__ void gbar(int target) {
    __syncthreads();
    if (threadIdx.x == 0) {
        __threadfence();
        atomicAdd(&g_cnt, 1);
        while (*(volatile int*)&g_cnt < target) __nanosleep(32);
    }
    __syncthreads();
}

// 64x64 tile, K=256, register-double-buffered loads. C = A@B^T(row-read)
__device__ void mtile(const float* A, const float* B, float* C, int bi, int bj,
                      __nv_bfloat16* AHI, __nv_bfloat16* ALO,
                      __nv_bfloat16* BHI, __nv_bfloat16* BLO) {
    const int tid = threadIdx.x, w = tid >> 5, lane = tid & 31;
    const int wm = w >> 2, wn = w & 3;
    const int l4 = lane >> 2, q2 = (lane & 3) * 2;

    float acc[2][2][4];
#pragma unroll
    for (int i = 0; i < 2; i++)
#pragma unroll
        for (int j = 0; j < 2; j++)
#pragma unroll
            for (int r = 0; r < 4; r++) acc[i][j][r] = 0.f;

    float4 va[2][4], vb[2][4];
#pragma unroll
    for (int it = 0; it < 4; it++) {
        int e = it * 256 + tid;
        int row = e >> 4, f4 = e & 15;
        va[0][it] = __ldcg((const float4*)(A + (size_t)(bi + row) * C_DIM + f4 * 4));
        vb[0][it] = __ldcg((const float4*)(B + (size_t)(bj + row) * C_DIM + f4 * 4));
    }

    for (int kc = 0; kc < 4; kc++) {
        const int cur = kc & 1;
#pragma unroll
        for (int it = 0; it < 4; it++) {
            int e = it * 256 + tid;
            int row = e >> 4, f4 = e & 15;
            cvt4(va[cur][it], AHI + row * PADK + f4 * 4, ALO + row * PADK + f4 * 4);
            cvt4(vb[cur][it], BHI + row * PADK + f4 * 4, BLO + row * PADK + f4 * 4);
        }
        __syncthreads();
        if (kc < 3) {
            const int k0n = (kc + 1) * 64;
#pragma unroll
            for (int it = 0; it < 4; it++) {
                int e = it * 256 + tid;
                int row = e >> 4, f4 = e & 15;
                va[cur ^ 1][it] = __ldcg((const float4*)(A + (size_t)(bi + row) * C_DIM + k0n + f4 * 4));
                vb[cur ^ 1][it] = __ldcg((const float4*)(B + (size_t)(bj + row) * C_DIM + k0n + f4 * 4));
            }
        }
#pragma unroll
        for (int ks = 0; ks < 4; ks++) {
            const int k0 = ks * 16;
            uint32_t bh[2][2], bl[2][2];
#pragma unroll
            for (int nt = 0; nt < 2; nt++) {
                ldb(bh[nt], BHI, wn * 16 + nt * 8, k0, l4, q2);
                ldb(bl[nt], BLO, wn * 16 + nt * 8, k0, l4, q2);
            }
#pragma unroll
            for (int mt = 0; mt < 2; mt++) {
                uint32_t ah[4], al[4];
                lda(ah, AHI, wm * 32 + mt * 16, k0, l4, q2);
                lda(al, ALO, wm * 32 + mt * 16, k0, l4, q2);
#pragma unroll
                for (int nt = 0; nt < 2; nt++) {
                    mma_bf16(acc[mt][nt], ah, bh[nt]);
                    mma_bf16(acc[mt][nt], ah, bl[nt]);
                    mma_bf16(acc[mt][nt], al, bh[nt]);
                }
            }
        }
        __syncthreads();
    }

#pragma unroll
    for (int mt = 0; mt < 2; mt++)
#pragma unroll
        for (int nt = 0; nt < 2; nt++) {
            int gi = bi + wm * 32 + mt * 16 + l4;
            int gj = bj + wn * 16 + nt * 8 + q2;
            *(float2*)(C + gi * C_DIM + gj) = make_float2(acc[mt][nt][0], acc[mt][nt][1]);
            *(float2*)(C + (gi + 8) * C_DIM + gj) = make_float2(acc[mt][nt][2], acc[mt][nt][3]);
        }
}

// 64x32 tile, K=256, all-CTA stages. mode 1: C=1.5C-0.5res  2: C=sc*res
__device__ void mtile32(const float* A, const float* B, float* C, int bi, int bj,
                        int mode, float sc,
                        __nv_bfloat16* AHI, __nv_bfloat16* ALO,
                        __nv_bfloat16* BHI, __nv_bfloat16* BLO) {
    const int tid = threadIdx.x, w = tid >> 5, lane = tid & 31;
    const int wm = w >> 1, wn = w & 1;
    const int l4 = lane >> 2, q2 = (lane & 3) * 2;

    float acc[2][4];
#pragma unroll
    for (int j = 0; j < 2; j++)
#pragma unroll
        for (int r = 0; r < 4; r++) acc[j][r] = 0.f;

    float4 va[2][4], vb[2][2];
#pragma unroll
    for (int it = 0; it < 4; it++) {
        int e = it * 256 + tid;
        int row = e >> 4, f4 = e & 15;
        va[0][it] = __ldcg((const float4*)(A + (size_t)(bi + row) * C_DIM + f4 * 4));
    }
#pragma unroll
    for (int it = 0; it < 2; it++) {
        int e = it * 256 + tid;
        int row = e >> 4, f4 = e & 15;
        vb[0][it] = __ldcg((const float4*)(B + (size_t)(bj + row) * C_DIM + f4 * 4));
    }

    for (int kc = 0; kc < 4; kc++) {
        const int cur = kc & 1;
#pragma unroll
        for (int it = 0; it < 4; it++) {
            int e = it * 256 + tid;
            int row = e >> 4, f4 = e & 15;
            cvt4(va[cur][it], AHI + row * PADK + f4 * 4, ALO + row * PADK + f4 * 4);
        }
#pragma unroll
        for (int it = 0; it < 2; it++) {
            int e = it * 256 + tid;
            int row = e >> 4, f4 = e & 15;
            cvt4(vb[cur][it], BHI + row * PADK + f4 * 4, BLO + row * PADK + f4 * 4);
        }
        __syncthreads();
        if (kc < 3) {
            const int k0n = (kc + 1) * 64;
#pragma unroll
            for (int it = 0; it < 4; it++) {
                int e = it * 256 + tid;
                int row = e >> 4, f4 = e & 15;
                va[cur ^ 1][it] = __ldcg((const float4*)(A + (size_t)(bi + row) * C_DIM + k0n + f4 * 4));
            }
#pragma unroll
            for (int it = 0; it < 2; it++) {
                int e = it * 256 + tid;
                int row = e >> 4, f4 = e & 15;
                vb[cur ^ 1][it] = __ldcg((const float4*)(B + (size_t)(bj + row) * C_DIM + k0n + f4 * 4));
            }
        }
#pragma unroll
        for (int ks = 0; ks < 4; ks++) {
            const int k0 = ks * 16;
            uint32_t ah[4], al[4];
            lda(ah, AHI, wm * 16, k0, l4, q2);
            lda(al, ALO, wm * 16, k0, l4, q2);
#pragma unroll
            for (int nt = 0; nt < 2; nt++) {
                uint32_t bh[2], bl[2];
                ldb(bh, BHI, wn * 16 + nt * 8, k0, l4, q2);
                ldb(bl, BLO, wn * 16 + nt * 8, k0, l4, q2);
                mma_bf16(acc[nt], ah, bh);
                mma_bf16(acc[nt], ah, bl);
                mma_bf16(acc[nt], al, bh);
            }
        }
        __syncthreads();
    }

#pragma unroll
    for (int nt = 0; nt < 2; nt++) {
        int gi = bi + wm * 16 + l4;
        int gj = bj + wn * 16 + nt * 8 + q2;
        float r0 = acc[nt][0], r1 = acc[nt][1], r2 = acc[nt][2], r3 = acc[nt][3];
        if (mode == 1) {
            float2 cA = __ldcg((const float2*)(C + gi * C_DIM + gj));
            float2 cB = __ldcg((const float2*)(C + (gi + 8) * C_DIM + gj));
            r0 = 1.5f * cA.x - 0.5f * r0;
            r1 = 1.5f * cA.y - 0.5f * r1;
            r2 = 1.5f * cB.x - 0.5f * r2;
            r3 = 1.5f * cB.y - 0.5f * r3;
        } else if (mode == 2) {
            r0 *= sc; r1 *= sc; r2 *= sc; r3 *= sc;
        }
        *(float2*)(C + gi * C_DIM + gj) = make_float2(r0, r1);
        *(float2*)(C + (gi + 8) * C_DIM + gj) = make_float2(r2, r3);
    }
}

__global__ __launch_bounds__(256, 1) void newton_fused(const float* __restrict__ R) {
    const int cta = blockIdx.x, tid = threadIdx.x;
    __shared__ __align__(16) __nv_bfloat16 sAHI[64 * PADK];
    __shared__ __align__(16) __nv_bfloat16 sALO[64 * PADK];
    __shared__ __align__(16) __nv_bfloat16 sBHI[64 * PADK];
    __shared__ __align__(16) __nv_bfloat16 sBLO[64 * PADK];
    __shared__ float sh[256];
    int st = 0;

    if (cta == 0) {
        sh[tid] = g_sigma[tid * (C_DIM + 1)];
        __syncthreads();
        for (int o = 128; o > 0; o >>= 1) {
            if (tid < o) sh[tid] += sh[tid + o];
            __syncthreads();
        }
        if (tid == 0) {
            float tr = 1.0f / sh[0];
            g_scal[0] = tr;
            g_scal[1] = sqrtf(tr);
        }
    }
    gbar(++st * NCTA);

    // SN = sigma*tr ; P1 = 1.5 I - 0.5 SN  (iteration 0 analytic)
    {
        float s0 = __ldcg(&g_scal[0]);
        for (int e = cta * 2048 + tid; e < (cta + 1) * 2048; e += 256) {
            int i = e >> 8, j = e & 255;
            float sn = g_sigma[e] * s0;
            g_SN[e] = sn;
            g_P[e] = ((i == j) ? 1.5f : 0.0f) - 0.5f * sn;
        }
    }
    gbar(++st * NCTA);

    const int t16 = cta & 15;
    const int bi64 = (t16 >> 2) * 64, bj64 = (t16 & 3) * 64;
    const int bi32 = (cta >> 3) * 64, bj32 = (cta & 7) * 32;

    for (int it = 0; it < 9; it++) {
        if (cta < 16)
            mtile(g_P, g_P, g_T, bi64, bj64, sAHI, sALO, sBHI, sBLO);
        else
            mtile(g_SN, g_P, g_QT, bi64, bj64, sAHI, sALO, sBHI, sBLO);
        gbar(++st * NCTA);
        mtile32(g_T, g_QT, g_P, bi32, bj32, 1, 0.f, sAHI, sALO, sBHI, sBLO);
        gbar(++st * NCTA);
    }

    mtile32(R, g_P, g_M, bi32, bj32, 2, __ldcg(&g_scal[1]), sAHI, sALO, sBHI, sBLO);
    gbar(++st * NCTA);

    for (int e = cta * 2048 + tid; e < (cta + 1) * 2048; e += 256) {
        float m = __ldcg(&g_M[e]);
        __nv_bfloat16 h = __float2bfloat16(m);
        g_Mhi[e] = h;
        g_Mlo[e] = __float2bfloat16(m - __bfloat162float(h));
    }
    for (int rr = 0; rr < 8; rr++) {
        int d = cta * 8 + rr;
        __syncthreads();
        sh[tid] = __ldcg(&g_M[d * C_DIM + tid]) * g_mean[tid];
        __syncthreads();
        for (int o = 128; o > 0; o >>= 1) {
            if (tid < o) sh[tid] += sh[tid + o];
            __syncthreads();
        }
        if (tid == 0) g_bvec[d] = sh[0];
    }
}

// ============== Out GEMM: both d-halves per CTA, X read once ==============
__global__ __launch_bounds__(256, 1)
void out_mma(const float* __restrict__ X, float* __restrict__ O) {
    extern __shared__ char sm[];
    const int mt = blockIdx.x, n = blockIdx.y;
    const int m0g = mt * 128;

    float* STG = (float*)sm;
    __nv_bfloat16* A0HI = (__nv_bfloat16*)(sm + 33792);
    __nv_bfloat16* A0LO = A0HI + 128 * PADK;
    __nv_bfloat16* A1HI = A0LO + 128 * PADK;
    __nv_bfloat16* A1LO = A1HI + 128 * PADK;
    __nv_bfloat16* BHI  = A1LO + 128 * PADK;
    __nv_bfloat16* BLO  = BHI + 128 * PADK;

    const int tid = threadIdx.x, w = tid >> 5, lane = tid & 31;
    const int wd = w >> 2, wm = w & 3;
    const int l4 = lane >> 2, q2 = (lane & 3) * 2;

    float acc[2][4][4][4];
#pragma unroll
    for (int h = 0; h < 2; h++)
#pragma unroll
        for (int i = 0; i < 4; i++)
#pragma unroll
            for (int j = 0; j < 4; j++)
#pragma unroll
                for (int r = 0; r < 4; r++) acc[h][i][j][r] = 0.f;

    for (int cc = 0; cc < 4; cc++) {
        const int c0 = cc * 64;
#pragma unroll
        for (int it = 0; it < 8; it++) {
            int e = it * 256 + tid;
            int row = e >> 5, j4 = e & 31;
            float4 v = *(const float4*)(X + ((size_t)(n * C_DIM + c0 + row)) * HW + m0g + j4 * 4);
            *(float4*)(STG + row * 132 + j4 * 4) = v;
        }
#pragma unroll
        for (int dh = 0; dh < 2; dh++) {
            __nv_bfloat16* AH = dh ? A1HI : A0HI;
            __nv_bfloat16* AL = dh ? A1LO : A0LO;
#pragma unroll
            for (int it = 0; it < 8; it++) {
                int e = it * 256 + tid;
                int row = e >> 4, u = e & 15;
                *(uint2*)(AH + row * PADK + u * 4) =
                    *(const uint2*)(g_Mhi + (size_t)(dh * 128 + row) * C_DIM + c0 + u * 4);
                *(uint2*)(AL + row * PADK + u * 4) =
                    *(const uint2*)(g_Mlo + (size_t)(dh * 128 + row) * C_DIM + c0 + u * 4);
            }
        }
        __syncthreads();
        {
            int m = tid & 127, half = tid >> 7;
#pragma unroll
            for (int o = 0; o < 4; o++) {
                int ocg = half * 4 + o;
                float f[8];
#pragma unroll
                for (int kk = 0; kk < 8; kk++) f[kk] = STG[(ocg * 8 + kk) * 132 + m];
                __nv_bfloat16 h[8], l[8];
#pragma unroll
                for (int kk = 0; kk < 8; kk++) split1(f[kk], h[kk], l[kk]);
                *(uint4*)(BHI + m * PADK + ocg * 8) =
                    make_uint4(packbf2(h[0], h[1]), packbf2(h[2], h[3]),
                               packbf2(h[4], h[5]), packbf2(h[6], h[7]));
                *(uint4*)(BLO + m * PADK + ocg * 8) =
                    make_uint4(packbf2(l[0], l[1]), packbf2(l[2], l[3]),
                               packbf2(l[4], l[5]), packbf2(l[6], l[7]));
            }
        }
        __syncthreads();
#pragma unroll
        for (int ks = 0; ks < 4; ks++) {
            const int k0 = ks * 16;
            uint32_t bh[4][2], bl[4][2];
#pragma unroll
            for (int nt = 0; nt < 4; nt++) {
                ldb(bh[nt], BHI, wm * 32 + nt * 8, k0, l4, q2);
                ldb(bl[nt], BLO, wm * 32 + nt * 8, k0, l4, q2);
            }
#pragma unroll
            for (int dh = 0; dh < 2; dh++) {
                const __nv_bfloat16* AH = dh ? A1HI : A0HI;
                const __nv_bfloat16* AL = dh ? A1LO : A0LO;
#pragma unroll
                for (int dt = 0; dt < 4; dt++) {
                    uint32_t ah[4], al[4];
                    lda(ah, AH, wd * 64 + dt * 16, k0, l4, q2);
                    lda(al, AL, wd * 64 + dt * 16, k0, l4, q2);
#pragma unroll
                    for (int nt = 0; nt < 4; nt++) {
                        mma_bf16(acc[dh][dt][nt], ah, bh[nt]);
                        mma_bf16(acc[dh][dt][nt], ah, bl[nt]);
                        mma_bf16(acc[dh][dt][nt], al, bh[nt]);
                    }
                }
            }
        }
        __syncthreads();
    }

    float* obase = O + (size_t)n * C_DIM * HW;
#pragma unroll
    for (int dh = 0; dh < 2; dh++)
#pragma unroll
        for (int dt = 0; dt < 4; dt++) {
            int d = dh * 128 + wd * 64 + dt * 16 + l4;
            float b0 = g_bvec[d], b8 = g_bvec[d + 8];
#pragma unroll
            for (int nt = 0; nt < 4; nt++) {
                int m = m0g + wm * 32 + nt * 8 + q2;
                __stcg((float2*)(obase + (size_t)d * HW + m),
                       make_float2(acc[dh][dt][nt][0] - b0, acc[dh][dt][nt][1] - b0));
                __stcg((float2*)(obase + (size_t)(d + 8) * HW + m),
                       make_float2(acc[dh][dt][nt][2] - b8, acc[dh][dt][nt][3] - b8));
            }
        }
}

// ---------------- launcher ------------------------------------------------
extern "C" void kernel_launch(void* const* d_in, const int* in_sizes, int n_in,
                              void* d_out, int out_size) {
    (void)in_sizes; (void)n_in; (void)out_size;
    const float* X = (const float*)d_in[0];
    const float* R = (const float*)d_in[1];
    float* O = (float*)d_out;

    cudaFuncSetAttribute(gram_mma, cudaFuncAttributeMaxDynamicSharedMemorySize, 73728);
    cudaFuncSetAttribute(out_mma, cudaFuncAttributeMaxDynamicSharedMemorySize, 144384);

    reset_kernel<<<1, 1>>>();
    gram_mma<<<dim3(3, N_IMG), 256, 73728>>>(X);
    meanp_kernel<<<1, 256>>>();
    sigma_reduce<<<dim3(3, 128), 128>>>();
    newton_fused<<<NCTA, 256>>>(R);
    out_mma<<<dim3(8, N_IMG), 256, 144384>>>(X, O);
}

// round 17
// speedup vs baseline: 2.9519x; 1.1836x over previous
#include <cuda_runtime.h>
#include <cuda_bf16.h>
#include <stdint.h>
#include <math.h>

#define C_DIM 256
#define HW    1024
#define N_IMG 64
#define M_TOT (N_IMG * HW)
#define EPSF  1e-5f
#define PADK 72
#define NCTA 64

__device__ float g_part[(size_t)3 * N_IMG * 128 * 128];
__device__ float g_msum[N_IMG * C_DIM];
__device__ float g_sigma[C_DIM * C_DIM];
__device__ float g_SN[C_DIM * C_DIM];
__device__ float g_P[C_DIM * C_DIM];
__device__ float g_T[C_DIM * C_DIM];
__device__ float g_QT[C_DIM * C_DIM];
__device__ float g_M[C_DIM * C_DIM];
__device__ __nv_bfloat16 g_Mhi[C_DIM * C_DIM];
__device__ __nv_bfloat16 g_Mlo[C_DIM * C_DIM];
__device__ float g_mean[C_DIM];
__device__ float g_bvec[C_DIM];
__device__ float g_scal[2];
__device__ int g_cnt;

// ======================= mma.sync helpers =================================
__device__ __forceinline__ void mma_bf16(float* c, const uint32_t* a, const uint32_t* b) {
    asm volatile(
        "mma.sync.aligned.m16n8k16.row.col.f32.bf16.bf16.f32 "
        "{%0,%1,%2,%3}, {%4,%5,%6,%7}, {%8,%9}, {%0,%1,%2,%3};"
        : "+f"(c[0]), "+f"(c[1]), "+f"(c[2]), "+f"(c[3])
        : "r"(a[0]), "r"(a[1]), "r"(a[2]), "r"(a[3]), "r"(b[0]), "r"(b[1]));
}
__device__ __forceinline__ uint32_t packbf2(__nv_bfloat16 a, __nv_bfloat16 b) {
    return (uint32_t)__bfloat16_as_ushort(a) | ((uint32_t)__bfloat16_as_ushort(b) << 16);
}
__device__ __forceinline__ void split1(float x, __nv_bfloat16& h, __nv_bfloat16& l) {
    h = __float2bfloat16(x);
    l = __float2bfloat16(x - __bfloat162float(h));
}
__device__ __forceinline__ void cvt4(const float4& v, void* hp, void* lp) {
    __nv_bfloat16 h0, h1, h2, h3, l0, l1, l2, l3;
    split1(v.x, h0, l0); split1(v.y, h1, l1);
    split1(v.z, h2, l2); split1(v.w, h3, l3);
    *(uint2*)hp = make_uint2(packbf2(h0, h1), packbf2(h2, h3));
    *(uint2*)lp = make_uint2(packbf2(l0, l1), packbf2(l2, l3));
}
__device__ __forceinline__ void lda(uint32_t* a, const __nv_bfloat16* t,
                                    int row, int k, int l4, int q2) {
    const __nv_bfloat16* p = t + (row + l4) * PADK + k + q2;
    a[0] = *(const uint32_t*)p;
    a[1] = *(const uint32_t*)(p + 8 * PADK);
    a[2] = *(const uint32_t*)(p + 8);
    a[3] = *(const uint32_t*)(p + 8 * PADK + 8);
}
__device__ __forceinline__ void ldb(uint32_t* b, const __nv_bfloat16* t,
                                    int n, int k, int l4, int q2) {
    const __nv_bfloat16* p = t + (n + l4) * PADK + k + q2;
    b[0] = *(const uint32_t*)p;
    b[1] = *(const uint32_t*)(p + 8);
}

// ================= Gram via mma.sync + fused mean partials ================
__global__ __launch_bounds__(256, 2)
void gram_mma(const float* __restrict__ X) {
    extern __shared__ char sm[];
    const int p = blockIdx.x, n = blockIdx.y;
    const int bi = (p == 2) ? 1 : 0;
    const int bj = (p == 0) ? 0 : 1;
    const bool diag = (bi == bj);

    __nv_bfloat16* AHI = (__nv_bfloat16*)sm;
    __nv_bfloat16* ALO = AHI + 128 * PADK;
    __nv_bfloat16* BHI = ALO + 128 * PADK;
    __nv_bfloat16* BLO = BHI + 128 * PADK;

    const int tid = threadIdx.x, w = tid >> 5, lane = tid & 31;
    const int wm = w >> 2, wn = w & 3;
    const int l4 = lane >> 2, q2 = (lane & 3) * 2;

    float acc[4][4][4];
#pragma unroll
    for (int i = 0; i < 4; i++)
#pragma unroll
        for (int j = 0; j < 4; j++)
#pragma unroll
            for (int r = 0; r < 4; r++) acc[i][j][r] = 0.f;

    float srow[8];
#pragma unroll
    for (int i = 0; i < 8; i++) srow[i] = 0.f;

    const __nv_bfloat16* Bh = diag ? AHI : BHI;
    const __nv_bfloat16* Bl = diag ? ALO : BLO;

    for (int kc = 0; kc < 16; kc++) {
        const int k0g = kc * 64;
        float4 v[4];
#pragma unroll
        for (int hb = 0; hb < 2; hb++) {
#pragma unroll
            for (int it = 0; it < 4; it++) {
                int e = (hb * 4 + it) * 256 + tid;
                int row = e >> 4, f4 = e & 15;
                v[it] = *(const float4*)(X + ((size_t)(n * C_DIM + bi * 128 + row)) * HW + k0g + f4 * 4);
            }
            if (diag)
#pragma unroll
                for (int it = 0; it < 4; it++)
                    srow[hb * 4 + it] += v[it].x + v[it].y + v[it].z + v[it].w;
#pragma unroll
            for (int it = 0; it < 4; it++) {
                int e = (hb * 4 + it) * 256 + tid;
                int row = e >> 4, f4 = e & 15;
                cvt4(v[it], AHI + row * PADK + f4 * 4, ALO + row * PADK + f4 * 4);
            }
        }
        if (!diag) {
#pragma unroll
            for (int hb = 0; hb < 2; hb++) {
#pragma unroll
                for (int it = 0; it < 4; it++) {
                    int e = (hb * 4 + it) * 256 + tid;
                    int row = e >> 4, f4 = e & 15;
                    v[it] = *(const float4*)(X + ((size_t)(n * C_DIM + bj * 128 + row)) * HW + k0g + f4 * 4);
                }
#pragma unroll
                for (int it = 0; it < 4; it++) {
                    int e = (hb * 4 + it) * 256 + tid;
                    int row = e >> 4, f4 = e & 15;
                    cvt4(v[it], BHI + row * PADK + f4 * 4, BLO + row * PADK + f4 * 4);
                }
            }
        }
        __syncthreads();
#pragma unroll
        for (int ks = 0; ks < 4; ks++) {
            const int k0 = ks * 16;
            uint32_t bh[4][2], bl[4][2];
#pragma unroll
            for (int nt = 0; nt < 4; nt++) {
                ldb(bh[nt], Bh, wn * 32 + nt * 8, k0, l4, q2);
                ldb(bl[nt], Bl, wn * 32 + nt * 8, k0, l4, q2);
            }
#pragma unroll
            for (int mt = 0; mt < 4; mt++) {
                uint32_t ah[4], al[4];
                lda(ah, AHI, wm * 64 + mt * 16, k0, l4, q2);
                lda(al, ALO, wm * 64 + mt * 16, k0, l4, q2);
#pragma unroll
                for (int nt = 0; nt < 4; nt++) {
                    mma_bf16(acc[mt][nt], ah, bh[nt]);
                    mma_bf16(acc[mt][nt], ah, bl[nt]);
                    mma_bf16(acc[mt][nt], al, bh[nt]);
                }
            }
        }
        __syncthreads();
    }

    if (diag) {
#pragma unroll
        for (int it = 0; it < 8; it++) {
            float sv = srow[it];
            sv += __shfl_xor_sync(0xffffffffu, sv, 1);
            sv += __shfl_xor_sync(0xffffffffu, sv, 2);
            sv += __shfl_xor_sync(0xffffffffu, sv, 4);
            sv += __shfl_xor_sync(0xffffffffu, sv, 8);
            if ((tid & 15) == 0)
                g_msum[n * C_DIM + bi * 128 + it * 16 + (tid >> 4)] = sv;
        }
    }

    float* outp = g_part + ((size_t)p * N_IMG + n) * 16384;
#pragma unroll
    for (int mt = 0; mt < 4; mt++)
#pragma unroll
        for (int nt = 0; nt < 4; nt++) {
            int i0 = wm * 64 + mt * 16 + l4;
            int j0 = wn * 32 + nt * 8 + q2;
            *(float2*)(outp + i0 * 128 + j0) = make_float2(acc[mt][nt][0], acc[mt][nt][1]);
            *(float2*)(outp + (i0 + 8) * 128 + j0) = make_float2(acc[mt][nt][2], acc[mt][nt][3]);
        }
}

// ---------------- fold per-image mean partials (+ reset barrier ctr) ------
__global__ void meanp_kernel() {
    int c = threadIdx.x;
    if (c == 0) g_cnt = 0;
    float s = 0.f;
#pragma unroll 8
    for (int n = 0; n < N_IMG; n++) s += g_msum[n * C_DIM + c];
    g_mean[c] = s * (1.0f / (float)M_TOT);
}

// ============== wide partial-reduce + Sigma build =========================
__global__ void sigma_reduce() {
    const int p = blockIdx.x, i = blockIdx.y, j = threadIdx.x;
    const int bi = (p == 2) ? 1 : 0;
    const int bj = (p == 0) ? 0 : 1;
    const float* src = g_part + (size_t)p * N_IMG * 16384 + i * 128 + j;
    float s = 0.f;
#pragma unroll 8
    for (int n = 0; n < N_IMG; n++) s += src[(size_t)n * 16384];
    int gi = bi * 128 + i, gj = bj * 128 + j;
    float v = s * (1.0f / (float)M_TOT) - g_mean[gi] * g_mean[gj];
    if (gi == gj) v += EPSF;
    g_sigma[gi * C_DIM + gj] = v;
    g_sigma[gj * C_DIM + gi] = v;
}

// =============== fused Newton cooperative kernel (tensor cores) ===========
__device__ __forceinline__ void gbar(int target) {
    __syncthreads();
    if (threadIdx.x == 0) {
        __threadfence();
        atomicAdd(&g_cnt, 1);
        while (*(volatile int*)&g_cnt < target) __nanosleep(32);
    }
    __syncthreads();
}

// 64x32 tile, K=256, double-buffered loads. mode 0: C = A@B^T(row-read)
__device__ void mtile6432(const float* A, const float* B, float* C, int bi, int bj,
                          __nv_bfloat16* AHI, __nv_bfloat16* ALO,
                          __nv_bfloat16* BHI, __nv_bfloat16* BLO) {
    const int tid = threadIdx.x, w = tid >> 5, lane = tid & 31;
    const int wm = w >> 1, wn = w & 1;
    const int l4 = lane >> 2, q2 = (lane & 3) * 2;

    float acc[2][4];
#pragma unroll
    for (int j = 0; j < 2; j++)
#pragma unroll
        for (int r = 0; r < 4; r++) acc[j][r] = 0.f;

    float4 va[2][4], vb[2][2];
#pragma unroll
    for (int it = 0; it < 4; it++) {
        int e = it * 256 + tid;
        int row = e >> 4, f4 = e & 15;
        va[0][it] = __ldcg((const float4*)(A + (size_t)(bi + row) * C_DIM + f4 * 4));
    }
#pragma unroll
    for (int it = 0; it < 2; it++) {
        int e = it * 256 + tid;
        int row = e >> 4, f4 = e & 15;
        vb[0][it] = __ldcg((const float4*)(B + (size_t)(bj + row) * C_DIM + f4 * 4));
    }

    for (int kc = 0; kc < 4; kc++) {
        const int cur = kc & 1;
#pragma unroll
        for (int it = 0; it < 4; it++) {
            int e = it * 256 + tid;
            int row = e >> 4, f4 = e & 15;
            cvt4(va[cur][it], AHI + row * PADK + f4 * 4, ALO + row * PADK + f4 * 4);
        }
#pragma unroll
        for (int it = 0; it < 2; it++) {
            int e = it * 256 + tid;
            int row = e >> 4, f4 = e & 15;
            cvt4(vb[cur][it], BHI + row * PADK + f4 * 4, BLO + row * PADK + f4 * 4);
        }
        __syncthreads();
        if (kc < 3) {
            const int k0n = (kc + 1) * 64;
#pragma unroll
            for (int it = 0; it < 4; it++) {
                int e = it * 256 + tid;
                int row = e >> 4, f4 = e & 15;
                va[cur ^ 1][it] = __ldcg((const float4*)(A + (size_t)(bi + row) * C_DIM + k0n + f4 * 4));
            }
#pragma unroll
            for (int it = 0; it < 2; it++) {
                int e = it * 256 + tid;
                int row = e >> 4, f4 = e & 15;
                vb[cur ^ 1][it] = __ldcg((const float4*)(B + (size_t)(bj + row) * C_DIM + k0n + f4 * 4));
            }
        }
#pragma unroll
        for (int ks = 0; ks < 4; ks++) {
            const int k0 = ks * 16;
            uint32_t ah[4], al[4];
            lda(ah, AHI, wm * 16, k0, l4, q2);
            lda(al, ALO, wm * 16, k0, l4, q2);
#pragma unroll
            for (int nt = 0; nt < 2; nt++) {
                uint32_t bh[2], bl[2];
                ldb(bh, BHI, wn * 16 + nt * 8, k0, l4, q2);
                ldb(bl, BLO, wn * 16 + nt * 8, k0, l4, q2);
                mma_bf16(acc[nt], ah, bh);
                mma_bf16(acc[nt], ah, bl);
                mma_bf16(acc[nt], al, bh);
            }
        }
        __syncthreads();
    }

#pragma unroll
    for (int nt = 0; nt < 2; nt++) {
        int gi = bi + wm * 16 + l4;
        int gj = bj + wn * 16 + nt * 8 + q2;
        *(float2*)(C + gi * C_DIM + gj) = make_float2(acc[nt][0], acc[nt][1]);
        *(float2*)(C + (gi + 8) * C_DIM + gj) = make_float2(acc[nt][2], acc[nt][3]);
    }
}

// 32x32 tile, K=256, double-buffered. mode 1: C=1.5C-0.5res  2: C=sc*res
__device__ void mtile3232(const float* A, const float* B, float* C, int bi, int bj,
                          int mode, float sc,
                          __nv_bfloat16* AHI, __nv_bfloat16* ALO,
                          __nv_bfloat16* BHI, __nv_bfloat16* BLO) {
    const int tid = threadIdx.x, w = tid >> 5, lane = tid & 31;
    const int wm = w >> 2, wn = w & 3;      // 2 x 4 warps: 16m x 8n each
    const int l4 = lane >> 2, q2 = (lane & 3) * 2;

    float acc[4];
#pragma unroll
    for (int r = 0; r < 4; r++) acc[r] = 0.f;

    float4 va[2][2], vb[2][2];
#pragma unroll
    for (int it = 0; it < 2; it++) {
        int e = it * 256 + tid;
        int row = e >> 4, f4 = e & 15;
        va[0][it] = __ldcg((const float4*)(A + (size_t)(bi + row) * C_DIM + f4 * 4));
        vb[0][it] = __ldcg((const float4*)(B + (size_t)(bj + row) * C_DIM + f4 * 4));
    }

    for (int kc = 0; kc < 4; kc++) {
        const int cur = kc & 1;
#pragma unroll
        for (int it = 0; it < 2; it++) {
            int e = it * 256 + tid;
            int row = e >> 4, f4 = e & 15;
            cvt4(va[cur][it], AHI + row * PADK + f4 * 4, ALO + row * PADK + f4 * 4);
            cvt4(vb[cur][it], BHI + row * PADK + f4 * 4, BLO + row * PADK + f4 * 4);
        }
        __syncthreads();
        if (kc < 3) {
            const int k0n = (kc + 1) * 64;
#pragma unroll
            for (int it = 0; it < 2; it++) {
                int e = it * 256 + tid;
                int row = e >> 4, f4 = e & 15;
                va[cur ^ 1][it] = __ldcg((const float4*)(A + (size_t)(bi + row) * C_DIM + k0n + f4 * 4));
                vb[cur ^ 1][it] = __ldcg((const float4*)(B + (size_t)(bj + row) * C_DIM + k0n + f4 * 4));
            }
        }
#pragma unroll
        for (int ks = 0; ks < 4; ks++) {
            const int k0 = ks * 16;
            uint32_t ah[4], al[4], bh[2], bl[2];
            lda(ah, AHI, wm * 16, k0, l4, q2);
            lda(al, ALO, wm * 16, k0, l4, q2);
            ldb(bh, BHI, wn * 8, k0, l4, q2);
            ldb(bl, BLO, wn * 8, k0, l4, q2);
            mma_bf16(acc, ah, bh);
            mma_bf16(acc, ah, bl);
            mma_bf16(acc, al, bh);
        }
        __syncthreads();
    }

    int gi = bi + wm * 16 + l4;
    int gj = bj + wn * 8 + q2;
    float r0 = acc[0], r1 = acc[1], r2 = acc[2], r3 = acc[3];
    if (mode == 1) {
        float2 cA = __ldcg((const float2*)(C + gi * C_DIM + gj));
        float2 cB = __ldcg((const float2*)(C + (gi + 8) * C_DIM + gj));
        r0 = 1.5f * cA.x - 0.5f * r0;
        r1 = 1.5f * cA.y - 0.5f * r1;
        r2 = 1.5f * cB.x - 0.5f * r2;
        r3 = 1.5f * cB.y - 0.5f * r3;
    } else if (mode == 2) {
        r0 *= sc; r1 *= sc; r2 *= sc; r3 *= sc;
    }
    *(float2*)(C + gi * C_DIM + gj) = make_float2(r0, r1);
    *(float2*)(C + (gi + 8) * C_DIM + gj) = make_float2(r2, r3);
}

__global__ __launch_bounds__(256, 1) void newton_fused(const float* __restrict__ R) {
    const int cta = blockIdx.x, tid = threadIdx.x;
    __shared__ __align__(16) __nv_bfloat16 sAHI[64 * PADK];
    __shared__ __align__(16) __nv_bfloat16 sALO[64 * PADK];
    __shared__ __align__(16) __nv_bfloat16 sBHI[64 * PADK];
    __shared__ __align__(16) __nv_bfloat16 sBLO[64 * PADK];
    __shared__ float sh[256];
    int st = 0;

    if (cta == 0) {
        sh[tid] = g_sigma[tid * (C_DIM + 1)];
        __syncthreads();
        for (int o = 128; o > 0; o >>= 1) {
            if (tid < o) sh[tid] += sh[tid + o];
            __syncthreads();
        }
        if (tid == 0) {
            float tr = 1.0f / sh[0];
            g_scal[0] = tr;
            g_scal[1] = sqrtf(tr);
        }
    }
    gbar(++st * NCTA);

    // SN = sigma*tr ; P1 = 1.5 I - 0.5 SN  (iteration 0 analytic)
    {
        float s0 = __ldcg(&g_scal[0]);
        for (int e = cta * 1024 + tid; e < (cta + 1) * 1024; e += 256) {
            int i = e >> 8, j = e & 255;
            float sn = g_sigma[e] * s0;
            g_SN[e] = sn;
            g_P[e] = ((i == j) ? 1.5f : 0.0f) - 0.5f * sn;
        }
    }
    gbar(++st * NCTA);

    // stage A: 64 tiles 64x32 (T: cta<32, QT: cta>=32)
    const int c32 = cta & 31;
    const int biA = (c32 >> 3) * 64, bjA = (c32 & 7) * 32;
    // stage B / M: 64 tiles 32x32
    const int biB = (cta >> 3) * 32, bjB = (cta & 7) * 32;

    for (int it = 0; it < 9; it++) {
        if (cta < 32)
            mtile6432(g_P, g_P, g_T, biA, bjA, sAHI, sALO, sBHI, sBLO);
        else
            mtile6432(g_SN, g_P, g_QT, biA, bjA, sAHI, sALO, sBHI, sBLO);
        gbar(++st * NCTA);
        mtile3232(g_T, g_QT, g_P, biB, bjB, 1, 0.f, sAHI, sALO, sBHI, sBLO);
        gbar(++st * NCTA);
    }

    mtile3232(R, g_P, g_M, biB, bjB, 2, __ldcg(&g_scal[1]), sAHI, sALO, sBHI, sBLO);
    gbar(++st * NCTA);

    for (int e = cta * 1024 + tid; e < (cta + 1) * 1024; e += 256) {
        float m = __ldcg(&g_M[e]);
        __nv_bfloat16 h = __float2bfloat16(m);
        g_Mhi[e] = h;
        g_Mlo[e] = __float2bfloat16(m - __bfloat162float(h));
    }
    for (int rr = 0; rr < 4; rr++) {
        int d = cta * 4 + rr;
        __syncthreads();
        sh[tid] = __ldcg(&g_M[d * C_DIM + tid]) * g_mean[tid];
        __syncthreads();
        for (int o = 128; o > 0; o >>= 1) {
            if (tid < o) sh[tid] += sh[tid + o];
            __syncthreads();
        }
        if (tid == 0) g_bvec[d] = sh[0];
    }
}

// ============== Out GEMM: both d-halves per CTA, X read once ==============
__global__ __launch_bounds__(256, 1)
void out_mma(const float* __restrict__ X, float* __restrict__ O) {
    extern __shared__ char sm[];
    const int mt = blockIdx.x, n = blockIdx.y;
    const int m0g = mt * 128;

    float* STG = (float*)sm;
    __nv_bfloat16* A0HI = (__nv_bfloat16*)(sm + 33792);
    __nv_bfloat16* A0LO = A0HI + 128 * PADK;
    __nv_bfloat16* A1HI = A0LO + 128 * PADK;
    __nv_bfloat16* A1LO = A1HI + 128 * PADK;
    __nv_bfloat16* BHI  = A1LO + 128 * PADK;
    __nv_bfloat16* BLO  = BHI + 128 * PADK;

    const int tid = threadIdx.x, w = tid >> 5, lane = tid & 31;
    const int wd = w >> 2, wm = w & 3;
    const int l4 = lane >> 2, q2 = (lane & 3) * 2;

    float acc[2][4][4][4];
#pragma unroll
    for (int h = 0; h < 2; h++)
#pragma unroll
        for (int i = 0; i < 4; i++)
#pragma unroll
            for (int j = 0; j < 4; j++)
#pragma unroll
                for (int r = 0; r < 4; r++) acc[h][i][j][r] = 0.f;

    for (int cc = 0; cc < 4; cc++) {
        const int c0 = cc * 64;
#pragma unroll
        for (int it = 0; it < 8; it++) {
            int e = it * 256 + tid;
            int row = e >> 5, j4 = e & 31;
            float4 v = *(const float4*)(X + ((size_t)(n * C_DIM + c0 + row)) * HW + m0g + j4 * 4);
            *(float4*)(STG + row * 132 + j4 * 4) = v;
        }
#pragma unroll
        for (int dh = 0; dh < 2; dh++) {
            __nv_bfloat16* AH = dh ? A1HI : A0HI;
            __nv_bfloat16* AL = dh ? A1LO : A0LO;
#pragma unroll
            for (int it = 0; it < 8; it++) {
                int e = it * 256 + tid;
                int row = e >> 4, u = e & 15;
                *(uint2*)(AH + row * PADK + u * 4) =
                    *(const uint2*)(g_Mhi + (size_t)(dh * 128 + row) * C_DIM + c0 + u * 4);
                *(uint2*)(AL + row * PADK + u * 4) =
                    *(const uint2*)(g_Mlo + (size_t)(dh * 128 + row) * C_DIM + c0 + u * 4);
            }
        }
        __syncthreads();
        {
            int m = tid & 127, half = tid >> 7;
#pragma unroll
            for (int o = 0; o < 4; o++) {
                int ocg = half * 4 + o;
                float f[8];
#pragma unroll
                for (int kk = 0; kk < 8; kk++) f[kk] = STG[(ocg * 8 + kk) * 132 + m];
                __nv_bfloat16 h[8], l[8];
#pragma unroll
                for (int kk = 0; kk < 8; kk++) split1(f[kk], h[kk], l[kk]);
                *(uint4*)(BHI + m * PADK + ocg * 8) =
                    make_uint4(packbf2(h[0], h[1]), packbf2(h[2], h[3]),
                               packbf2(h[4], h[5]), packbf2(h[6], h[7]));
                *(uint4*)(BLO + m * PADK + ocg * 8) =
                    make_uint4(packbf2(l[0], l[1]), packbf2(l[2], l[3]),
                               packbf2(l[4], l[5]), packbf2(l[6], l[7]));
            }
        }
        __syncthreads();
#pragma unroll
        for (int ks = 0; ks < 4; ks++) {
            const int k0 = ks * 16;
            uint32_t bh[4][2], bl[4][2];
#pragma unroll
            for (int nt = 0; nt < 4; nt++) {
                ldb(bh[nt], BHI, wm * 32 + nt * 8, k0, l4, q2);
                ldb(bl[nt], BLO, wm * 32 + nt * 8, k0, l4, q2);
            }
#pragma unroll
            for (int dh = 0; dh < 2; dh++) {
                const __nv_bfloat16* AH = dh ? A1HI : A0HI;
                const __nv_bfloat16* AL = dh ? A1LO : A0LO;
#pragma unroll
                for (int dt = 0; dt < 4; dt++) {
                    uint32_t ah[4], al[4];
                    lda(ah, AH, wd * 64 + dt * 16, k0, l4, q2);
                    lda(al, AL, wd * 64 + dt * 16, k0, l4, q2);
#pragma unroll
                    for (int nt = 0; nt < 4; nt++) {
                        mma_bf16(acc[dh][dt][nt], ah, bh[nt]);
                        mma_bf16(acc[dh][dt][nt], ah, bl[nt]);
                        mma_bf16(acc[dh][dt][nt], al, bh[nt]);
                    }
                }
            }
        }
        __syncthreads();
    }

    float* obase = O + (size_t)n * C_DIM * HW;
#pragma unroll
    for (int dh = 0; dh < 2; dh++)
#pragma unroll
        for (int dt = 0; dt < 4; dt++) {
            int d = dh * 128 + wd * 64 + dt * 16 + l4;
            float b0 = g_bvec[d], b8 = g_bvec[d + 8];
#pragma unroll
            for (int nt = 0; nt < 4; nt++) {
                int m = m0g + wm * 32 + nt * 8 + q2;
                __stcg((float2*)(obase + (size_t)d * HW + m),
                       make_float2(acc[dh][dt][nt][0] - b0, acc[dh][dt][nt][1] - b0));
                __stcg((float2*)(obase + (size_t)(d + 8) * HW + m),
                       make_float2(acc[dh][dt][nt][2] - b8, acc[dh][dt][nt][3] - b8));
            }
        }
}

// ---------------- launcher ------------------------------------------------
extern "C" void kernel_launch(void* const* d_in, const int* in_sizes, int n_in,
                              void* d_out, int out_size) {
    (void)in_sizes; (void)n_in; (void)out_size;
    const float* X = (const float*)d_in[0];
    const float* R = (const float*)d_in[1];
    float* O = (float*)d_out;

    cudaFuncSetAttribute(gram_mma, cudaFuncAttributeMaxDynamicSharedMemorySize, 73728);
    cudaFuncSetAttribute(out_mma, cudaFuncAttributeMaxDynamicSharedMemorySize, 144384);

    gram_mma<<<dim3(3, N_IMG), 256, 73728>>>(X);
    meanp_kernel<<<1, 256>>>();
    sigma_reduce<<<dim3(3, 128), 128>>>();
    newton_fused<<<NCTA, 256>>>(R);
    out_mma<<<dim3(8, N_IMG), 256, 144384>>>(X, O);
}